// round 9
// baseline (speedup 1.0000x reference)
#include <cuda_runtime.h>
#include <cuda_fp16.h>
#include <cstdint>

// value[b] = -( x[b] . MLP(x[b]) )^2 — fp16 HMMA GEMM chain.
// R9: single __syncthreads per k-iteration (wait0->sync->prefetch->compute),
//     warp-parity k-chunk stagger to spread the post-barrier LDSM burst.

__device__ __half g_Whi[442368];
__device__ __half g_Wlo[442368];
__device__ __half g_actA[65536UL * 512];
__device__ __half g_actB[65536UL * 512];

__device__ __forceinline__ uint32_t smem_u32(const void* p) {
    uint32_t a;
    asm("{ .reg .u64 t; cvta.to.shared.u64 t, %1; cvt.u32.u64 %0, t; }" : "=r"(a) : "l"(p));
    return a;
}
__device__ __forceinline__ void ldsm4(uint32_t* r, uint32_t addr) {
    asm volatile("ldmatrix.sync.aligned.m8n8.x4.shared.b16 {%0,%1,%2,%3}, [%4];"
        : "=r"(r[0]), "=r"(r[1]), "=r"(r[2]), "=r"(r[3]) : "r"(addr));
}
__device__ __forceinline__ void mma_f16(float* c, const uint32_t* a, const uint32_t* b) {
    asm volatile("mma.sync.aligned.m16n8k16.row.col.f32.f16.f16.f32 "
        "{%0,%1,%2,%3}, {%4,%5,%6,%7}, {%8,%9}, {%0,%1,%2,%3};"
        : "+f"(c[0]), "+f"(c[1]), "+f"(c[2]), "+f"(c[3])
        : "r"(a[0]), "r"(a[1]), "r"(a[2]), "r"(a[3]), "r"(b[0]), "r"(b[1]));
}
#define CP16(dst, src)  asm volatile("cp.async.cg.shared.global [%0], [%1], 16;" :: "r"(dst), "l"(src))
#define CP_COMMIT()     asm volatile("cp.async.commit_group;" ::: "memory")
#define CP_WAIT0()      asm volatile("cp.async.wait_group 0;" ::: "memory")

__device__ __forceinline__ uint32_t packh2(__half a, __half b) {
    return (uint32_t)__half_as_ushort(a) | ((uint32_t)__half_as_ushort(b) << 16);
}
__device__ __forceinline__ void split1h(float v, __half& h, __half& l) {
    h = __float2half_rn(v);
    l = __float2half_rn(v - __half2float(h));
}

__global__ void split_all(const float* __restrict__ W1, const float* __restrict__ W2,
                          const float* __restrict__ W3, const float* __restrict__ W4) {
    int i = blockIdx.x * blockDim.x + threadIdx.x;
    if (i >= 442368) return;
    float w;
    if (i < 32768)       w = W1[i];
    else if (i < 294912) w = W2[i - 32768];
    else if (i < 425984) w = W3[i - 294912];
    else                 w = W4[i - 425984];
    __half h, l; split1h(w, h, l);
    g_Whi[i] = h; g_Wlo[i] = l;
}

// ============================ Layer 1: x(f32,K=64) -> 512, ELU ============================
__global__ void __launch_bounds__(256, 2)
l1_kernel(const float* __restrict__ x, const float* __restrict__ bias,
          __half* __restrict__ out)
{
    extern __shared__ char sm[];
    // [0,8192) A | [8192,73728) W bufs 2x(hi16K+lo16K) | [73728,75776) bias
    const int tid = threadIdx.x, wid = tid >> 5, l = tid & 31;
    const long base = (long)blockIdx.x * 64;
    const uint32_t smb = smem_u32(sm);

    auto prefW = [&](int nt, int buf) {
        const int n0 = nt * 128;
        #pragma unroll
        for (int i = tid; i < 2048; i += 256) {
            const int plane = i >> 10, j = i & 1023;
            const int n = j >> 3, c = j & 7;
            const __half* src = (plane ? g_Wlo : g_Whi) + (n0 + n) * 64 + c * 8;
            CP16(smb + 8192 + buf * 32768 + plane * 16384 + n * 128 + ((uint32_t)(c ^ (n & 7)) << 4), src);
        }
    };

    prefW(0, 0); CP_COMMIT();

    #pragma unroll
    for (int i = tid; i < 1024; i += 256) {
        const int r = i >> 4, k4 = (i & 15) * 4;
        const int c = k4 >> 3, wi = (k4 & 4) << 1;
        const float4 v = *(const float4*)(x + (base + r) * 64 + k4);
        const uint32_t off = r * 128 + ((uint32_t)(c ^ (r & 7)) << 4) + wi;
        *(uint32_t*)(sm + off)     = packh2(__float2half_rn(v.x), __float2half_rn(v.y));
        *(uint32_t*)(sm + off + 4) = packh2(__float2half_rn(v.z), __float2half_rn(v.w));
    }
    for (int i = tid; i < 512; i += 256) *(float*)(sm + 73728 + i * 4) = bias[i];

    const int wM = (wid & 1) * 32, wN = (wid >> 1) * 32;
    const int aRow = wM + (l & 15), aCk = l >> 4;
    const uint32_t aSel = (uint32_t)(aRow & 7);
    const int bnLoc = (l & 7) | ((l & 16) >> 1), bcLoc = (l >> 3) & 1;
    const int sOff = (wid & 1) << 1;     // warp-parity k-chunk stagger

    #pragma unroll 1
    for (int nt = 0; nt < 4; nt++) {
        CP_WAIT0();
        __syncthreads();
        if (nt + 1 < 4) { prefW(nt + 1, (nt + 1) & 1); CP_COMMIT(); }
        const uint32_t wb = smb + 8192 + (nt & 1) * 32768;

        float acc[32];
        #pragma unroll
        for (int q = 0; q < 32; q++) acc[q] = 0.0f;

        #pragma unroll
        for (int si = 0; si < 4; si++) {
            const int s = (si + sOff) & 3;
            const int ck = s * 2 + aCk;
            uint32_t ah[2][4];
            #pragma unroll
            for (int mt = 0; mt < 2; mt++)
                ldsm4(ah[mt], smb + (aRow + mt * 16) * 128 + ((uint32_t)(ck ^ aSel) << 4));
            const int bc = s * 2 + bcLoc;
            uint32_t bh[4][2], bl[4][2], t[4];
            #pragma unroll
            for (int pp = 0; pp < 2; pp++) {
                const int n = wN + 16 * pp + bnLoc;
                const uint32_t ba = wb + n * 128 + ((uint32_t)(bc ^ (n & 7)) << 4);
                ldsm4(t, ba);
                bh[2*pp][0]=t[0]; bh[2*pp][1]=t[1]; bh[2*pp+1][0]=t[2]; bh[2*pp+1][1]=t[3];
                ldsm4(t, ba + 16384);
                bl[2*pp][0]=t[0]; bl[2*pp][1]=t[1]; bl[2*pp+1][0]=t[2]; bl[2*pp+1][1]=t[3];
            }
            #pragma unroll
            for (int mt = 0; mt < 2; mt++) {
                float* am = acc + mt * 16;
                #pragma unroll
                for (int u = 0; u < 4; u++) mma_f16(am + 4*u, ah[mt], bh[u]);
                #pragma unroll
                for (int u = 0; u < 4; u++) mma_f16(am + 4*u, ah[mt], bl[u]);
            }
        }
        #pragma unroll
        for (int mt = 0; mt < 2; mt++) {
            const int r0 = wM + mt * 16 + (l >> 2);
            #pragma unroll
            for (int j = 0; j < 4; j++) {
                const int col = nt * 128 + wN + j * 8 + (l & 3) * 2;
                const float b0 = *(const float*)(sm + 73728 + col * 4);
                const float b1 = *(const float*)(sm + 73728 + col * 4 + 4);
                const int q = mt * 16 + j * 4;
                float v00 = acc[q+0] + b0, v01 = acc[q+1] + b1;
                float v10 = acc[q+2] + b0, v11 = acc[q+3] + b1;
                v00 = v00 > 0.f ? v00 : expm1f(v00);
                v01 = v01 > 0.f ? v01 : expm1f(v01);
                v10 = v10 > 0.f ? v10 : expm1f(v10);
                v11 = v11 > 0.f ? v11 : expm1f(v11);
                *(uint32_t*)(out + (base + r0) * 512 + col)     = packh2(__float2half_rn(v00), __float2half_rn(v01));
                *(uint32_t*)(out + (base + r0 + 8) * 512 + col) = packh2(__float2half_rn(v10), __float2half_rn(v11));
            }
        }
    }
}

// ============================ Mid layers: K=512 -> N (ELU) ============================
template<int N>
__global__ void __launch_bounds__(256, 2)
mid_kernel(const __half* __restrict__ in, int woff, const float* __restrict__ bias,
           __half* __restrict__ out)
{
    extern __shared__ char sm[];
    constexpr int K = 512, KT = 8, NITER = (N / 128) * KT;
    constexpr int BIASOFF = 81920;

    const int tid = threadIdx.x, wid = tid >> 5, l = tid & 31;
    const long base = (long)blockIdx.x * 64;
    const uint32_t smb = smem_u32(sm);

    auto prefetch = [&](int it, int buf) {
        const int nt = it / KT, kt = it % KT;
        const int k0 = kt * 64, n0 = nt * 128;
        #pragma unroll
        for (int i = tid; i < 512; i += 256) {
            const int r = i >> 3, c = i & 7;
            const __half* src = in + (base + r) * K + k0 + c * 8;
            CP16(smb + buf * 8192 + r * 128 + ((uint32_t)(c ^ (r & 7)) << 4), src);
        }
        #pragma unroll
        for (int i = tid; i < 2048; i += 256) {
            const int plane = i >> 10, j = i & 1023;
            const int n = j >> 3, c = j & 7;
            const __half* src = (plane ? g_Wlo : g_Whi) + woff + (long)(n0 + n) * K + k0 + c * 8;
            CP16(smb + 16384 + buf * 32768 + plane * 16384 + n * 128 + ((uint32_t)(c ^ (n & 7)) << 4), src);
        }
    };

    prefetch(0, 0); CP_COMMIT();
    for (int i = tid; i < N; i += 256) *(float*)(sm + BIASOFF + i * 4) = bias[i];

    const int wM = (wid & 1) * 32, wN = (wid >> 1) * 32;
    const int aRow = wM + (l & 15), aCk = l >> 4;
    const uint32_t aSel = (uint32_t)(aRow & 7);
    const int bnLoc = (l & 7) | ((l & 16) >> 1), bcLoc = (l >> 3) & 1;
    const int sOff = (wid & 1) << 1;

    float acc[32];

    #pragma unroll 1
    for (int it = 0; it < NITER; ++it) {
        const int nt = it / KT, kt = it % KT;
        CP_WAIT0();
        __syncthreads();
        if (it + 1 < NITER) { prefetch(it + 1, (it + 1) & 1); CP_COMMIT(); }
        if (kt == 0) {
            #pragma unroll
            for (int q = 0; q < 32; q++) acc[q] = 0.0f;
        }
        const uint32_t ab = smb + (it & 1) * 8192;
        const uint32_t wb = smb + 16384 + (it & 1) * 32768;
        #pragma unroll
        for (int si = 0; si < 4; si++) {
            const int s = (si + sOff) & 3;
            const int ck = s * 2 + aCk;
            uint32_t ah[2][4];
            #pragma unroll
            for (int mt = 0; mt < 2; mt++)
                ldsm4(ah[mt], ab + (aRow + mt * 16) * 128 + ((uint32_t)(ck ^ aSel) << 4));
            const int bc = s * 2 + bcLoc;
            uint32_t bh[4][2], bl[4][2], t[4];
            #pragma unroll
            for (int pp = 0; pp < 2; pp++) {
                const int n = wN + 16 * pp + bnLoc;
                const uint32_t ba = wb + n * 128 + ((uint32_t)(bc ^ (n & 7)) << 4);
                ldsm4(t, ba);
                bh[2*pp][0]=t[0]; bh[2*pp][1]=t[1]; bh[2*pp+1][0]=t[2]; bh[2*pp+1][1]=t[3];
                ldsm4(t, ba + 16384);
                bl[2*pp][0]=t[0]; bl[2*pp][1]=t[1]; bl[2*pp+1][0]=t[2]; bl[2*pp+1][1]=t[3];
            }
            #pragma unroll
            for (int mt = 0; mt < 2; mt++) {
                float* am = acc + mt * 16;
                #pragma unroll
                for (int u = 0; u < 4; u++) mma_f16(am + 4*u, ah[mt], bh[u]);
                #pragma unroll
                for (int u = 0; u < 4; u++) mma_f16(am + 4*u, ah[mt], bl[u]);
            }
        }
        if (kt == KT - 1) {
            #pragma unroll
            for (int mt = 0; mt < 2; mt++) {
                const int r0 = wM + mt * 16 + (l >> 2);
                #pragma unroll
                for (int j = 0; j < 4; j++) {
                    const int col = nt * 128 + wN + j * 8 + (l & 3) * 2;
                    const float b0 = *(const float*)(sm + BIASOFF + col * 4);
                    const float b1 = *(const float*)(sm + BIASOFF + col * 4 + 4);
                    const int q = mt * 16 + j * 4;
                    float v00 = acc[q+0] + b0, v01 = acc[q+1] + b1;
                    float v10 = acc[q+2] + b0, v11 = acc[q+3] + b1;
                    v00 = v00 > 0.f ? v00 : expm1f(v00);
                    v01 = v01 > 0.f ? v01 : expm1f(v01);
                    v10 = v10 > 0.f ? v10 : expm1f(v10);
                    v11 = v11 > 0.f ? v11 : expm1f(v11);
                    *(uint32_t*)(out + (base + r0) * N + col)     = packh2(__float2half_rn(v00), __float2half_rn(v01));
                    *(uint32_t*)(out + (base + r0 + 8) * N + col) = packh2(__float2half_rn(v10), __float2half_rn(v11));
                }
            }
        }
    }
}

// ============================ Layer 4 + fused dot: K=256 -> 64, out=-(x.z)^2 ============================
__global__ void __launch_bounds__(256, 2)
l4_kernel(const __half* __restrict__ in, const float* __restrict__ bias,
          const float* __restrict__ x, float* __restrict__ outv)
{
    extern __shared__ char sm[];
    constexpr int KT = 4;
    const int tid = threadIdx.x, wid = tid >> 5, l = tid & 31;
    const long base = (long)blockIdx.x * 64;
    const uint32_t smb = smem_u32(sm);

    auto prefA = [&](int kt, int buf) {
        const int k0 = kt * 64;
        #pragma unroll
        for (int i = tid; i < 512; i += 256) {
            const int r = i >> 3, c = i & 7;
            const __half* src = in + (base + r) * 256 + k0 + c * 8;
            CP16(smb + buf * 8192 + r * 128 + ((uint32_t)(c ^ (r & 7)) << 4), src);
        }
    };

    #pragma unroll
    for (int i = tid; i < 4096; i += 256) {
        const int plane = i >> 11, j = i & 2047;
        const int n = j >> 5, c = j & 31;
        const __half* src = (plane ? g_Wlo : g_Whi) + 425984 + n * 256 + c * 8;
        CP16(smb + 16384 + plane * 32768 + n * 512 + (((uint32_t)(c ^ (n & 7))) << 4), src);
    }
    prefA(0, 0); CP_COMMIT();
    if (tid < 64) *(float*)(sm + 81920 + tid * 4) = bias[tid];

    const int wM = (wid & 1) * 32, wN = (wid >> 1) * 16;
    const int aRow = wM + (l & 15), aCk = l >> 4;
    const uint32_t aSel = (uint32_t)(aRow & 7);
    const int bnLoc = (l & 7) | ((l & 16) >> 1), bcLoc = (l >> 3) & 1;
    const int sOff = (wid & 1) << 1;

    float acc[16];
    #pragma unroll
    for (int q = 0; q < 16; q++) acc[q] = 0.0f;

    #pragma unroll 1
    for (int kt = 0; kt < KT; ++kt) {
        CP_WAIT0();
        __syncthreads();
        if (kt + 1 < KT) { prefA(kt + 1, (kt + 1) & 1); CP_COMMIT(); }
        const uint32_t ab = smb + (kt & 1) * 8192;
        #pragma unroll
        for (int si = 0; si < 4; si++) {
            const int s = (si + sOff) & 3;
            const int ck = s * 2 + aCk;
            uint32_t ah[2][4];
            #pragma unroll
            for (int mt = 0; mt < 2; mt++)
                ldsm4(ah[mt], ab + (aRow + mt * 16) * 128 + ((uint32_t)(ck ^ aSel) << 4));
            const int bck = kt * 8 + s * 2 + bcLoc;
            uint32_t bh[2][2], bl[2][2], t[4];
            {
                const int n = wN + bnLoc;
                const uint32_t ba = smb + 16384 + n * 512 + ((uint32_t)(bck ^ (n & 7)) << 4);
                ldsm4(t, ba);
                bh[0][0]=t[0]; bh[0][1]=t[1]; bh[1][0]=t[2]; bh[1][1]=t[3];
                ldsm4(t, ba + 32768);
                bl[0][0]=t[0]; bl[0][1]=t[1]; bl[1][0]=t[2]; bl[1][1]=t[3];
            }
            #pragma unroll
            for (int mt = 0; mt < 2; mt++) {
                float* am = acc + mt * 8;
                mma_f16(am + 0, ah[mt], bh[0]);
                mma_f16(am + 4, ah[mt], bh[1]);
            }
            #pragma unroll
            for (int mt = 0; mt < 2; mt++) {
                float* am = acc + mt * 8;
                mma_f16(am + 0, ah[mt], bl[0]);
                mma_f16(am + 4, ah[mt], bl[1]);
            }
        }
    }

    float* zsum = (float*)(sm + 82176);
    #pragma unroll
    for (int mt = 0; mt < 2; mt++) {
        const int r0 = wM + mt * 16 + (l >> 2);
        float p0 = 0.0f, p1 = 0.0f;
        #pragma unroll
        for (int u = 0; u < 2; u++) {
            const int col = wN + u * 8 + (l & 3) * 2;
            const float b0 = *(const float*)(sm + 81920 + col * 4);
            const float b1 = *(const float*)(sm + 81920 + col * 4 + 4);
            const int q = mt * 8 + u * 4;
            const float2 x0 = *(const float2*)(x + (base + r0) * 64 + col);
            const float2 x1 = *(const float2*)(x + (base + r0 + 8) * 64 + col);
            p0 += (acc[q+0] + b0) * x0.x + (acc[q+1] + b1) * x0.y;
            p1 += (acc[q+2] + b0) * x1.x + (acc[q+3] + b1) * x1.y;
        }
        p0 += __shfl_xor_sync(0xFFFFFFFF, p0, 1);
        p0 += __shfl_xor_sync(0xFFFFFFFF, p0, 2);
        p1 += __shfl_xor_sync(0xFFFFFFFF, p1, 1);
        p1 += __shfl_xor_sync(0xFFFFFFFF, p1, 2);
        if ((l & 3) == 0) {
            zsum[r0 * 4 + (wid >> 1)]       = p0;
            zsum[(r0 + 8) * 4 + (wid >> 1)] = p1;
        }
    }
    __syncthreads();
    if (tid < 64) {
        const float s = zsum[tid * 4] + zsum[tid * 4 + 1] + zsum[tid * 4 + 2] + zsum[tid * 4 + 3];
        outv[base + tid] = -s * s;
    }
}

extern "C" void kernel_launch(void* const* d_in, const int* in_sizes, int n_in,
                              void* d_out, int out_size)
{
    const float* x  = (const float*)d_in[0];
    const float* W1 = (const float*)d_in[1];
    const float* b1 = (const float*)d_in[2];
    const float* W2 = (const float*)d_in[3];
    const float* b2 = (const float*)d_in[4];
    const float* W3 = (const float*)d_in[5];
    const float* b3 = (const float*)d_in[6];
    const float* W4 = (const float*)d_in[7];
    const float* b4 = (const float*)d_in[8];
    float* out = (float*)d_out;

    __half *actA, *actB;
    cudaGetSymbolAddress((void**)&actA, g_actA);
    cudaGetSymbolAddress((void**)&actB, g_actB);

    split_all<<<(442368 + 511) / 512, 512>>>(W1, W2, W3, W4);

    constexpr int SZ1 = 75776;
    constexpr int SZM5 = 83968;
    constexpr int SZM2 = 82944;
    constexpr int SZ4 = 83200;
    cudaFuncSetAttribute(l1_kernel,       cudaFuncAttributeMaxDynamicSharedMemorySize, SZ1);
    cudaFuncSetAttribute(mid_kernel<512>, cudaFuncAttributeMaxDynamicSharedMemorySize, SZM5);
    cudaFuncSetAttribute(mid_kernel<256>, cudaFuncAttributeMaxDynamicSharedMemorySize, SZM2);
    cudaFuncSetAttribute(l4_kernel,       cudaFuncAttributeMaxDynamicSharedMemorySize, SZ4);

    const int grid = 65536 / 64;  // 1024
    l1_kernel<<<grid, 256, SZ1>>>(x, b1, actA);
    mid_kernel<512><<<grid, 256, SZM5>>>(actA, 32768,  b2, actB);
    mid_kernel<256><<<grid, 256, SZM2>>>(actB, 294912, b3, actA);
    l4_kernel<<<grid, 256, SZ4>>>(actA, b4, x, out);
}

// round 10
// speedup vs baseline: 1.2878x; 1.2878x over previous
#include <cuda_runtime.h>
#include <cuda_fp16.h>
#include <cstdint>

// value[b] = -( x[b] . MLP(x[b]) )^2 — fp16 HMMA GEMM chain.
// R10: L2/L3 use single-fp16 W (1 MMA per k16, 44.5% less MMA work);
//      L1/L4 keep W hi/lo split (2 MMAs) to preserve error budget.

__device__ __half g_Whi[442368];
__device__ __half g_Wlo[442368];
__device__ __half g_actA[65536UL * 512];
__device__ __half g_actB[65536UL * 512];

__device__ __forceinline__ uint32_t smem_u32(const void* p) {
    uint32_t a;
    asm("{ .reg .u64 t; cvta.to.shared.u64 t, %1; cvt.u32.u64 %0, t; }" : "=r"(a) : "l"(p));
    return a;
}
__device__ __forceinline__ void ldsm4(uint32_t* r, uint32_t addr) {
    asm volatile("ldmatrix.sync.aligned.m8n8.x4.shared.b16 {%0,%1,%2,%3}, [%4];"
        : "=r"(r[0]), "=r"(r[1]), "=r"(r[2]), "=r"(r[3]) : "r"(addr));
}
__device__ __forceinline__ void mma_f16(float* c, const uint32_t* a, const uint32_t* b) {
    asm volatile("mma.sync.aligned.m16n8k16.row.col.f32.f16.f16.f32 "
        "{%0,%1,%2,%3}, {%4,%5,%6,%7}, {%8,%9}, {%0,%1,%2,%3};"
        : "+f"(c[0]), "+f"(c[1]), "+f"(c[2]), "+f"(c[3])
        : "r"(a[0]), "r"(a[1]), "r"(a[2]), "r"(a[3]), "r"(b[0]), "r"(b[1]));
}
#define CP16(dst, src)  asm volatile("cp.async.cg.shared.global [%0], [%1], 16;" :: "r"(dst), "l"(src))
#define CP_COMMIT()     asm volatile("cp.async.commit_group;" ::: "memory")
#define CP_WAIT0()      asm volatile("cp.async.wait_group 0;" ::: "memory")

__device__ __forceinline__ uint32_t packh2(__half a, __half b) {
    return (uint32_t)__half_as_ushort(a) | ((uint32_t)__half_as_ushort(b) << 16);
}
__device__ __forceinline__ void split1h(float v, __half& h, __half& l) {
    h = __float2half_rn(v);
    l = __float2half_rn(v - __half2float(h));
}

__global__ void split_all(const float* __restrict__ W1, const float* __restrict__ W2,
                          const float* __restrict__ W3, const float* __restrict__ W4) {
    int i = blockIdx.x * blockDim.x + threadIdx.x;
    if (i >= 442368) return;
    float w;
    if (i < 32768)       w = W1[i];
    else if (i < 294912) w = W2[i - 32768];
    else if (i < 425984) w = W3[i - 294912];
    else                 w = W4[i - 425984];
    __half h, l; split1h(w, h, l);
    g_Whi[i] = h; g_Wlo[i] = l;
}

// ============================ Layer 1: x(f32,K=64) -> 512, ELU (W hi/lo) ============================
__global__ void __launch_bounds__(256, 2)
l1_kernel(const float* __restrict__ x, const float* __restrict__ bias,
          __half* __restrict__ out)
{
    extern __shared__ char sm[];
    // [0,8192) A | [8192,73728) W bufs 2x(hi16K+lo16K) | [73728,75776) bias
    const int tid = threadIdx.x, wid = tid >> 5, l = tid & 31;
    const long base = (long)blockIdx.x * 64;
    const uint32_t smb = smem_u32(sm);

    auto prefW = [&](int nt, int buf) {
        const int n0 = nt * 128;
        #pragma unroll
        for (int i = tid; i < 2048; i += 256) {
            const int plane = i >> 10, j = i & 1023;
            const int n = j >> 3, c = j & 7;
            const __half* src = (plane ? g_Wlo : g_Whi) + (n0 + n) * 64 + c * 8;
            CP16(smb + 8192 + buf * 32768 + plane * 16384 + n * 128 + ((uint32_t)(c ^ (n & 7)) << 4), src);
        }
    };

    prefW(0, 0); CP_COMMIT();

    #pragma unroll
    for (int i = tid; i < 1024; i += 256) {
        const int r = i >> 4, k4 = (i & 15) * 4;
        const int c = k4 >> 3, wi = (k4 & 4) << 1;
        const float4 v = *(const float4*)(x + (base + r) * 64 + k4);
        const uint32_t off = r * 128 + ((uint32_t)(c ^ (r & 7)) << 4) + wi;
        *(uint32_t*)(sm + off)     = packh2(__float2half_rn(v.x), __float2half_rn(v.y));
        *(uint32_t*)(sm + off + 4) = packh2(__float2half_rn(v.z), __float2half_rn(v.w));
    }
    for (int i = tid; i < 512; i += 256) *(float*)(sm + 73728 + i * 4) = bias[i];

    const int wM = (wid & 1) * 32, wN = (wid >> 1) * 32;
    const int aRow = wM + (l & 15), aCk = l >> 4;
    const uint32_t aSel = (uint32_t)(aRow & 7);
    const int bnLoc = (l & 7) | ((l & 16) >> 1), bcLoc = (l >> 3) & 1;
    const int sOff = (wid & 1) << 1;

    #pragma unroll 1
    for (int nt = 0; nt < 4; nt++) {
        CP_WAIT0();
        __syncthreads();
        if (nt + 1 < 4) { prefW(nt + 1, (nt + 1) & 1); CP_COMMIT(); }
        const uint32_t wb = smb + 8192 + (nt & 1) * 32768;

        float acc[32];
        #pragma unroll
        for (int q = 0; q < 32; q++) acc[q] = 0.0f;

        #pragma unroll
        for (int si = 0; si < 4; si++) {
            const int s = (si + sOff) & 3;
            const int ck = s * 2 + aCk;
            uint32_t ah[2][4];
            #pragma unroll
            for (int mt = 0; mt < 2; mt++)
                ldsm4(ah[mt], smb + (aRow + mt * 16) * 128 + ((uint32_t)(ck ^ aSel) << 4));
            const int bc = s * 2 + bcLoc;
            uint32_t bh[4][2], bl[4][2], t[4];
            #pragma unroll
            for (int pp = 0; pp < 2; pp++) {
                const int n = wN + 16 * pp + bnLoc;
                const uint32_t ba = wb + n * 128 + ((uint32_t)(bc ^ (n & 7)) << 4);
                ldsm4(t, ba);
                bh[2*pp][0]=t[0]; bh[2*pp][1]=t[1]; bh[2*pp+1][0]=t[2]; bh[2*pp+1][1]=t[3];
                ldsm4(t, ba + 16384);
                bl[2*pp][0]=t[0]; bl[2*pp][1]=t[1]; bl[2*pp+1][0]=t[2]; bl[2*pp+1][1]=t[3];
            }
            #pragma unroll
            for (int mt = 0; mt < 2; mt++) {
                float* am = acc + mt * 16;
                #pragma unroll
                for (int u = 0; u < 4; u++) mma_f16(am + 4*u, ah[mt], bh[u]);
                #pragma unroll
                for (int u = 0; u < 4; u++) mma_f16(am + 4*u, ah[mt], bl[u]);
            }
        }
        #pragma unroll
        for (int mt = 0; mt < 2; mt++) {
            const int r0 = wM + mt * 16 + (l >> 2);
            #pragma unroll
            for (int j = 0; j < 4; j++) {
                const int col = nt * 128 + wN + j * 8 + (l & 3) * 2;
                const float b0 = *(const float*)(sm + 73728 + col * 4);
                const float b1 = *(const float*)(sm + 73728 + col * 4 + 4);
                const int q = mt * 16 + j * 4;
                float v00 = acc[q+0] + b0, v01 = acc[q+1] + b1;
                float v10 = acc[q+2] + b0, v11 = acc[q+3] + b1;
                v00 = v00 > 0.f ? v00 : expm1f(v00);
                v01 = v01 > 0.f ? v01 : expm1f(v01);
                v10 = v10 > 0.f ? v10 : expm1f(v10);
                v11 = v11 > 0.f ? v11 : expm1f(v11);
                *(uint32_t*)(out + (base + r0) * 512 + col)     = packh2(__float2half_rn(v00), __float2half_rn(v01));
                *(uint32_t*)(out + (base + r0 + 8) * 512 + col) = packh2(__float2half_rn(v10), __float2half_rn(v11));
            }
        }
    }
}

// ============================ Mid layers: K=512 -> N (ELU), single-fp16 W ============================
template<int N>
__global__ void __launch_bounds__(256, 2)
mid_kernel(const __half* __restrict__ in, int woff, const float* __restrict__ bias,
           __half* __restrict__ out)
{
    extern __shared__ char sm[];
    constexpr int K = 512, KT = 8, NITER = (N / 128) * KT;
    // [0,16384) A bufs 2x8K | [16384,49152) W bufs 2x16K | [49152,...) bias
    constexpr int BIASOFF = 49152;

    const int tid = threadIdx.x, wid = tid >> 5, l = tid & 31;
    const long base = (long)blockIdx.x * 64;
    const uint32_t smb = smem_u32(sm);

    auto prefetch = [&](int it, int buf) {
        const int nt = it / KT, kt = it % KT;
        const int k0 = kt * 64, n0 = nt * 128;
        #pragma unroll
        for (int i = tid; i < 512; i += 256) {         // A: 64 rows x 8 chunks
            const int r = i >> 3, c = i & 7;
            const __half* src = in + (base + r) * K + k0 + c * 8;
            CP16(smb + buf * 8192 + r * 128 + ((uint32_t)(c ^ (r & 7)) << 4), src);
        }
        #pragma unroll
        for (int i = tid; i < 1024; i += 256) {        // W hi only: 128 rows x 8 chunks
            const int n = i >> 3, c = i & 7;
            const __half* src = g_Whi + woff + (long)(n0 + n) * K + k0 + c * 8;
            CP16(smb + 16384 + buf * 16384 + n * 128 + ((uint32_t)(c ^ (n & 7)) << 4), src);
        }
    };

    prefetch(0, 0); CP_COMMIT();
    for (int i = tid; i < N; i += 256) *(float*)(sm + BIASOFF + i * 4) = bias[i];

    const int wM = (wid & 1) * 32, wN = (wid >> 1) * 32;
    const int aRow = wM + (l & 15), aCk = l >> 4;
    const uint32_t aSel = (uint32_t)(aRow & 7);
    const int bnLoc = (l & 7) | ((l & 16) >> 1), bcLoc = (l >> 3) & 1;
    const int sOff = (wid & 1) << 1;

    float acc[32];

    #pragma unroll 1
    for (int it = 0; it < NITER; ++it) {
        const int nt = it / KT, kt = it % KT;
        CP_WAIT0();
        __syncthreads();
        if (it + 1 < NITER) { prefetch(it + 1, (it + 1) & 1); CP_COMMIT(); }
        if (kt == 0) {
            #pragma unroll
            for (int q = 0; q < 32; q++) acc[q] = 0.0f;
        }
        const uint32_t ab = smb + (it & 1) * 8192;
        const uint32_t wb = smb + 16384 + (it & 1) * 16384;
        #pragma unroll
        for (int si = 0; si < 4; si++) {
            const int s = (si + sOff) & 3;
            const int ck = s * 2 + aCk;
            uint32_t ah[2][4];
            #pragma unroll
            for (int mt = 0; mt < 2; mt++)
                ldsm4(ah[mt], ab + (aRow + mt * 16) * 128 + ((uint32_t)(ck ^ aSel) << 4));
            const int bc = s * 2 + bcLoc;
            uint32_t bh[4][2], t[4];
            #pragma unroll
            for (int pp = 0; pp < 2; pp++) {
                const int n = wN + 16 * pp + bnLoc;
                const uint32_t ba = wb + n * 128 + ((uint32_t)(bc ^ (n & 7)) << 4);
                ldsm4(t, ba);
                bh[2*pp][0]=t[0]; bh[2*pp][1]=t[1]; bh[2*pp+1][0]=t[2]; bh[2*pp+1][1]=t[3];
            }
            #pragma unroll
            for (int mt = 0; mt < 2; mt++) {
                float* am = acc + mt * 16;
                #pragma unroll
                for (int u = 0; u < 4; u++) mma_f16(am + 4*u, ah[mt], bh[u]);
            }
        }
        if (kt == KT - 1) {
            #pragma unroll
            for (int mt = 0; mt < 2; mt++) {
                const int r0 = wM + mt * 16 + (l >> 2);
                #pragma unroll
                for (int j = 0; j < 4; j++) {
                    const int col = nt * 128 + wN + j * 8 + (l & 3) * 2;
                    const float b0 = *(const float*)(sm + BIASOFF + col * 4);
                    const float b1 = *(const float*)(sm + BIASOFF + col * 4 + 4);
                    const int q = mt * 16 + j * 4;
                    float v00 = acc[q+0] + b0, v01 = acc[q+1] + b1;
                    float v10 = acc[q+2] + b0, v11 = acc[q+3] + b1;
                    v00 = v00 > 0.f ? v00 : expm1f(v00);
                    v01 = v01 > 0.f ? v01 : expm1f(v01);
                    v10 = v10 > 0.f ? v10 : expm1f(v10);
                    v11 = v11 > 0.f ? v11 : expm1f(v11);
                    *(uint32_t*)(out + (base + r0) * N + col)     = packh2(__float2half_rn(v00), __float2half_rn(v01));
                    *(uint32_t*)(out + (base + r0 + 8) * N + col) = packh2(__float2half_rn(v10), __float2half_rn(v11));
                }
            }
        }
    }
}

// ============================ Layer 4 + fused dot: K=256 -> 64 (W hi/lo) ============================
__global__ void __launch_bounds__(256, 2)
l4_kernel(const __half* __restrict__ in, const float* __restrict__ bias,
          const float* __restrict__ x, float* __restrict__ outv)
{
    extern __shared__ char sm[];
    constexpr int KT = 4;
    const int tid = threadIdx.x, wid = tid >> 5, l = tid & 31;
    const long base = (long)blockIdx.x * 64;
    const uint32_t smb = smem_u32(sm);

    auto prefA = [&](int kt, int buf) {
        const int k0 = kt * 64;
        #pragma unroll
        for (int i = tid; i < 512; i += 256) {
            const int r = i >> 3, c = i & 7;
            const __half* src = in + (base + r) * 256 + k0 + c * 8;
            CP16(smb + buf * 8192 + r * 128 + ((uint32_t)(c ^ (r & 7)) << 4), src);
        }
    };

    #pragma unroll
    for (int i = tid; i < 4096; i += 256) {
        const int plane = i >> 11, j = i & 2047;
        const int n = j >> 5, c = j & 31;
        const __half* src = (plane ? g_Wlo : g_Whi) + 425984 + n * 256 + c * 8;
        CP16(smb + 16384 + plane * 32768 + n * 512 + (((uint32_t)(c ^ (n & 7))) << 4), src);
    }
    prefA(0, 0); CP_COMMIT();
    if (tid < 64) *(float*)(sm + 81920 + tid * 4) = bias[tid];

    const int wM = (wid & 1) * 32, wN = (wid >> 1) * 16;
    const int aRow = wM + (l & 15), aCk = l >> 4;
    const uint32_t aSel = (uint32_t)(aRow & 7);
    const int bnLoc = (l & 7) | ((l & 16) >> 1), bcLoc = (l >> 3) & 1;
    const int sOff = (wid & 1) << 1;

    float acc[16];
    #pragma unroll
    for (int q = 0; q < 16; q++) acc[q] = 0.0f;

    #pragma unroll 1
    for (int kt = 0; kt < KT; ++kt) {
        CP_WAIT0();
        __syncthreads();
        if (kt + 1 < KT) { prefA(kt + 1, (kt + 1) & 1); CP_COMMIT(); }
        const uint32_t ab = smb + (kt & 1) * 8192;
        #pragma unroll
        for (int si = 0; si < 4; si++) {
            const int s = (si + sOff) & 3;
            const int ck = s * 2 + aCk;
            uint32_t ah[2][4];
            #pragma unroll
            for (int mt = 0; mt < 2; mt++)
                ldsm4(ah[mt], ab + (aRow + mt * 16) * 128 + ((uint32_t)(ck ^ aSel) << 4));
            const int bck = kt * 8 + s * 2 + bcLoc;
            uint32_t bh[2][2], bl[2][2], t[4];
            {
                const int n = wN + bnLoc;
                const uint32_t ba = smb + 16384 + n * 512 + ((uint32_t)(bck ^ (n & 7)) << 4);
                ldsm4(t, ba);
                bh[0][0]=t[0]; bh[0][1]=t[1]; bh[1][0]=t[2]; bh[1][1]=t[3];
                ldsm4(t, ba + 32768);
                bl[0][0]=t[0]; bl[0][1]=t[1]; bl[1][0]=t[2]; bl[1][1]=t[3];
            }
            #pragma unroll
            for (int mt = 0; mt < 2; mt++) {
                float* am = acc + mt * 8;
                mma_f16(am + 0, ah[mt], bh[0]);
                mma_f16(am + 4, ah[mt], bh[1]);
            }
            #pragma unroll
            for (int mt = 0; mt < 2; mt++) {
                float* am = acc + mt * 8;
                mma_f16(am + 0, ah[mt], bl[0]);
                mma_f16(am + 4, ah[mt], bl[1]);
            }
        }
    }

    float* zsum = (float*)(sm + 82176);
    #pragma unroll
    for (int mt = 0; mt < 2; mt++) {
        const int r0 = wM + mt * 16 + (l >> 2);
        float p0 = 0.0f, p1 = 0.0f;
        #pragma unroll
        for (int u = 0; u < 2; u++) {
            const int col = wN + u * 8 + (l & 3) * 2;
            const float b0 = *(const float*)(sm + 81920 + col * 4);
            const float b1 = *(const float*)(sm + 81920 + col * 4 + 4);
            const int q = mt * 8 + u * 4;
            const float2 x0 = *(const float2*)(x + (base + r0) * 64 + col);
            const float2 x1 = *(const float2*)(x + (base + r0 + 8) * 64 + col);
            p0 += (acc[q+0] + b0) * x0.x + (acc[q+1] + b1) * x0.y;
            p1 += (acc[q+2] + b0) * x1.x + (acc[q+3] + b1) * x1.y;
        }
        p0 += __shfl_xor_sync(0xFFFFFFFF, p0, 1);
        p0 += __shfl_xor_sync(0xFFFFFFFF, p0, 2);
        p1 += __shfl_xor_sync(0xFFFFFFFF, p1, 1);
        p1 += __shfl_xor_sync(0xFFFFFFFF, p1, 2);
        if ((l & 3) == 0) {
            zsum[r0 * 4 + (wid >> 1)]       = p0;
            zsum[(r0 + 8) * 4 + (wid >> 1)] = p1;
        }
    }
    __syncthreads();
    if (tid < 64) {
        const float s = zsum[tid * 4] + zsum[tid * 4 + 1] + zsum[tid * 4 + 2] + zsum[tid * 4 + 3];
        outv[base + tid] = -s * s;
    }
}

extern "C" void kernel_launch(void* const* d_in, const int* in_sizes, int n_in,
                              void* d_out, int out_size)
{
    const float* x  = (const float*)d_in[0];
    const float* W1 = (const float*)d_in[1];
    const float* b1 = (const float*)d_in[2];
    const float* W2 = (const float*)d_in[3];
    const float* b2 = (const float*)d_in[4];
    const float* W3 = (const float*)d_in[5];
    const float* b3 = (const float*)d_in[6];
    const float* W4 = (const float*)d_in[7];
    const float* b4 = (const float*)d_in[8];
    float* out = (float*)d_out;

    __half *actA, *actB;
    cudaGetSymbolAddress((void**)&actA, g_actA);
    cudaGetSymbolAddress((void**)&actB, g_actB);

    split_all<<<(442368 + 511) / 512, 512>>>(W1, W2, W3, W4);

    constexpr int SZ1 = 75776;   // 8K A + 64K W bufs + 2K bias
    constexpr int SZM5 = 51200;  // 16K A bufs + 32K W bufs + 2K bias
    constexpr int SZM2 = 50176;  // ... + 1K bias
    constexpr int SZ4 = 83200;   // 16K A bufs + 64K W + 256B bias + 1K zsum
    cudaFuncSetAttribute(l1_kernel,       cudaFuncAttributeMaxDynamicSharedMemorySize, SZ1);
    cudaFuncSetAttribute(mid_kernel<512>, cudaFuncAttributeMaxDynamicSharedMemorySize, SZM5);
    cudaFuncSetAttribute(mid_kernel<256>, cudaFuncAttributeMaxDynamicSharedMemorySize, SZM2);
    cudaFuncSetAttribute(l4_kernel,       cudaFuncAttributeMaxDynamicSharedMemorySize, SZ4);

    const int grid = 65536 / 64;  // 1024
    l1_kernel<<<grid, 256, SZ1>>>(x, b1, actA);
    mid_kernel<512><<<grid, 256, SZM5>>>(actA, 32768,  b2, actB);
    mid_kernel<256><<<grid, 256, SZM2>>>(actB, 294912, b3, actA);
    l4_kernel<<<grid, 256, SZ4>>>(actA, b4, x, out);
}

// round 11
// speedup vs baseline: 1.4104x; 1.0953x over previous
#include <cuda_runtime.h>
#include <cuda_fp16.h>
#include <cstdint>

// value[b] = -( x[b] . MLP(x[b]) )^2 — fp16 HMMA GEMM chain.
// R11: mid kernels K-outer / 2 n-tiles inner (acc[64]) -> A-ldsm reuse,
//      2x MMAs per barrier, half the A traffic. L1/L4 keep W hi/lo.

__device__ __half g_Whi[442368];
__device__ __half g_Wlo[442368];
__device__ __half g_actA[65536UL * 512];
__device__ __half g_actB[65536UL * 512];

__device__ __forceinline__ uint32_t smem_u32(const void* p) {
    uint32_t a;
    asm("{ .reg .u64 t; cvta.to.shared.u64 t, %1; cvt.u32.u64 %0, t; }" : "=r"(a) : "l"(p));
    return a;
}
__device__ __forceinline__ void ldsm4(uint32_t* r, uint32_t addr) {
    asm volatile("ldmatrix.sync.aligned.m8n8.x4.shared.b16 {%0,%1,%2,%3}, [%4];"
        : "=r"(r[0]), "=r"(r[1]), "=r"(r[2]), "=r"(r[3]) : "r"(addr));
}
__device__ __forceinline__ void mma_f16(float* c, const uint32_t* a, const uint32_t* b) {
    asm volatile("mma.sync.aligned.m16n8k16.row.col.f32.f16.f16.f32 "
        "{%0,%1,%2,%3}, {%4,%5,%6,%7}, {%8,%9}, {%0,%1,%2,%3};"
        : "+f"(c[0]), "+f"(c[1]), "+f"(c[2]), "+f"(c[3])
        : "r"(a[0]), "r"(a[1]), "r"(a[2]), "r"(a[3]), "r"(b[0]), "r"(b[1]));
}
#define CP16(dst, src)  asm volatile("cp.async.cg.shared.global [%0], [%1], 16;" :: "r"(dst), "l"(src))
#define CP_COMMIT()     asm volatile("cp.async.commit_group;" ::: "memory")
#define CP_WAIT0()      asm volatile("cp.async.wait_group 0;" ::: "memory")

__device__ __forceinline__ uint32_t packh2(__half a, __half b) {
    return (uint32_t)__half_as_ushort(a) | ((uint32_t)__half_as_ushort(b) << 16);
}
__device__ __forceinline__ void split1h(float v, __half& h, __half& l) {
    h = __float2half_rn(v);
    l = __float2half_rn(v - __half2float(h));
}

__global__ void split_all(const float* __restrict__ W1, const float* __restrict__ W2,
                          const float* __restrict__ W3, const float* __restrict__ W4) {
    int i = blockIdx.x * blockDim.x + threadIdx.x;
    if (i >= 442368) return;
    float w;
    if (i < 32768)       w = W1[i];
    else if (i < 294912) w = W2[i - 32768];
    else if (i < 425984) w = W3[i - 294912];
    else                 w = W4[i - 425984];
    __half h, l; split1h(w, h, l);
    g_Whi[i] = h; g_Wlo[i] = l;
}

// ============================ Layer 1: x(f32,K=64) -> 512, ELU (W hi/lo) ============================
__global__ void __launch_bounds__(256, 2)
l1_kernel(const float* __restrict__ x, const float* __restrict__ bias,
          __half* __restrict__ out)
{
    extern __shared__ char sm[];
    const int tid = threadIdx.x, wid = tid >> 5, l = tid & 31;
    const long base = (long)blockIdx.x * 64;
    const uint32_t smb = smem_u32(sm);

    auto prefW = [&](int nt, int buf) {
        const int n0 = nt * 128;
        #pragma unroll
        for (int i = tid; i < 2048; i += 256) {
            const int plane = i >> 10, j = i & 1023;
            const int n = j >> 3, c = j & 7;
            const __half* src = (plane ? g_Wlo : g_Whi) + (n0 + n) * 64 + c * 8;
            CP16(smb + 8192 + buf * 32768 + plane * 16384 + n * 128 + ((uint32_t)(c ^ (n & 7)) << 4), src);
        }
    };

    prefW(0, 0); CP_COMMIT();

    #pragma unroll
    for (int i = tid; i < 1024; i += 256) {
        const int r = i >> 4, k4 = (i & 15) * 4;
        const int c = k4 >> 3, wi = (k4 & 4) << 1;
        const float4 v = *(const float4*)(x + (base + r) * 64 + k4);
        const uint32_t off = r * 128 + ((uint32_t)(c ^ (r & 7)) << 4) + wi;
        *(uint32_t*)(sm + off)     = packh2(__float2half_rn(v.x), __float2half_rn(v.y));
        *(uint32_t*)(sm + off + 4) = packh2(__float2half_rn(v.z), __float2half_rn(v.w));
    }
    for (int i = tid; i < 512; i += 256) *(float*)(sm + 73728 + i * 4) = bias[i];

    const int wM = (wid & 1) * 32, wN = (wid >> 1) * 32;
    const int aRow = wM + (l & 15), aCk = l >> 4;
    const uint32_t aSel = (uint32_t)(aRow & 7);
    const int bnLoc = (l & 7) | ((l & 16) >> 1), bcLoc = (l >> 3) & 1;
    const int sOff = (wid & 1) << 1;

    #pragma unroll 1
    for (int nt = 0; nt < 4; nt++) {
        CP_WAIT0();
        __syncthreads();
        if (nt + 1 < 4) { prefW(nt + 1, (nt + 1) & 1); CP_COMMIT(); }
        const uint32_t wb = smb + 8192 + (nt & 1) * 32768;

        float acc[32];
        #pragma unroll
        for (int q = 0; q < 32; q++) acc[q] = 0.0f;

        #pragma unroll
        for (int si = 0; si < 4; si++) {
            const int s = (si + sOff) & 3;
            const int ck = s * 2 + aCk;
            uint32_t ah[2][4];
            #pragma unroll
            for (int mt = 0; mt < 2; mt++)
                ldsm4(ah[mt], smb + (aRow + mt * 16) * 128 + ((uint32_t)(ck ^ aSel) << 4));
            const int bc = s * 2 + bcLoc;
            uint32_t bh[4][2], bl[4][2], t[4];
            #pragma unroll
            for (int pp = 0; pp < 2; pp++) {
                const int n = wN + 16 * pp + bnLoc;
                const uint32_t ba = wb + n * 128 + ((uint32_t)(bc ^ (n & 7)) << 4);
                ldsm4(t, ba);
                bh[2*pp][0]=t[0]; bh[2*pp][1]=t[1]; bh[2*pp+1][0]=t[2]; bh[2*pp+1][1]=t[3];
                ldsm4(t, ba + 16384);
                bl[2*pp][0]=t[0]; bl[2*pp][1]=t[1]; bl[2*pp+1][0]=t[2]; bl[2*pp+1][1]=t[3];
            }
            #pragma unroll
            for (int mt = 0; mt < 2; mt++) {
                float* am = acc + mt * 16;
                #pragma unroll
                for (int u = 0; u < 4; u++) mma_f16(am + 4*u, ah[mt], bh[u]);
                #pragma unroll
                for (int u = 0; u < 4; u++) mma_f16(am + 4*u, ah[mt], bl[u]);
            }
        }
        #pragma unroll
        for (int mt = 0; mt < 2; mt++) {
            const int r0 = wM + mt * 16 + (l >> 2);
            #pragma unroll
            for (int j = 0; j < 4; j++) {
                const int col = nt * 128 + wN + j * 8 + (l & 3) * 2;
                const float b0 = *(const float*)(sm + 73728 + col * 4);
                const float b1 = *(const float*)(sm + 73728 + col * 4 + 4);
                const int q = mt * 16 + j * 4;
                float v00 = acc[q+0] + b0, v01 = acc[q+1] + b1;
                float v10 = acc[q+2] + b0, v11 = acc[q+3] + b1;
                v00 = v00 > 0.f ? v00 : expm1f(v00);
                v01 = v01 > 0.f ? v01 : expm1f(v01);
                v10 = v10 > 0.f ? v10 : expm1f(v10);
                v11 = v11 > 0.f ? v11 : expm1f(v11);
                *(uint32_t*)(out + (base + r0) * 512 + col)     = packh2(__float2half_rn(v00), __float2half_rn(v01));
                *(uint32_t*)(out + (base + r0 + 8) * 512 + col) = packh2(__float2half_rn(v10), __float2half_rn(v11));
            }
        }
    }
}

// ============================ Mid layers: K=512 -> N (ELU), single-fp16 W ============================
// K-outer: each warp accumulates 2 n-tiles (acc[64]) per 256-wide n-group.
template<int N>
__global__ void __launch_bounds__(256, 2)
mid_kernel(const __half* __restrict__ in, int woff, const float* __restrict__ bias,
           __half* __restrict__ out)
{
    extern __shared__ char sm[];
    constexpr int K = 512, KT = 8, NG = N / 256, NITER = NG * KT;
    // [0,16384) A bufs 2x8K | [16384,81920) W bufs 2x32K (256 n-rows) | [81920,..) bias
    constexpr int BIASOFF = 81920;

    const int tid = threadIdx.x, wid = tid >> 5, l = tid & 31;
    const long base = (long)blockIdx.x * 64;
    const uint32_t smb = smem_u32(sm);

    auto prefetch = [&](int it, int buf) {
        const int ng = it / KT, kt = it % KT;
        const int k0 = kt * 64, n0 = ng * 256;
        #pragma unroll
        for (int i = tid; i < 512; i += 256) {         // A: 64 rows x 8 chunks
            const int r = i >> 3, c = i & 7;
            const __half* src = in + (base + r) * K + k0 + c * 8;
            CP16(smb + buf * 8192 + r * 128 + ((uint32_t)(c ^ (r & 7)) << 4), src);
        }
        #pragma unroll
        for (int i = tid; i < 2048; i += 256) {        // W: 256 n-rows x 8 chunks
            const int n = i >> 3, c = i & 7;
            const __half* src = g_Whi + woff + (long)(n0 + n) * K + k0 + c * 8;
            CP16(smb + 16384 + buf * 32768 + n * 128 + ((uint32_t)(c ^ (n & 7)) << 4), src);
        }
    };

    prefetch(0, 0); CP_COMMIT();
    for (int i = tid; i < N; i += 256) *(float*)(sm + BIASOFF + i * 4) = bias[i];

    const int wM = (wid & 1) * 32, wN = (wid >> 1) * 32;
    const int aRow = wM + (l & 15), aCk = l >> 4;
    const uint32_t aSel = (uint32_t)(aRow & 7);
    const int bnLoc = (l & 7) | ((l & 16) >> 1), bcLoc = (l >> 3) & 1;
    const int sOff = (wid & 1) << 1;

    float acc[64];   // [mt2][tile2][u4][4]

    #pragma unroll 1
    for (int it = 0; it < NITER; ++it) {
        const int ng = it / KT, kt = it % KT;
        CP_WAIT0();
        __syncthreads();
        if (it + 1 < NITER) { prefetch(it + 1, (it + 1) & 1); CP_COMMIT(); }
        if (kt == 0) {
            #pragma unroll
            for (int q = 0; q < 64; q++) acc[q] = 0.0f;
        }
        const uint32_t ab = smb + (it & 1) * 8192;
        const uint32_t wb = smb + 16384 + (it & 1) * 32768;
        #pragma unroll
        for (int si = 0; si < 4; si++) {
            const int s = (si + sOff) & 3;
            const int ck = s * 2 + aCk;
            uint32_t ah[2][4];
            #pragma unroll
            for (int mt = 0; mt < 2; mt++)
                ldsm4(ah[mt], ab + (aRow + mt * 16) * 128 + ((uint32_t)(ck ^ aSel) << 4));
            const int bc = s * 2 + bcLoc;
            uint32_t bh[8][2], t[4];
            #pragma unroll
            for (int tl = 0; tl < 2; tl++) {
                #pragma unroll
                for (int pp = 0; pp < 2; pp++) {
                    const int n = tl * 128 + wN + 16 * pp + bnLoc;
                    const uint32_t ba = wb + n * 128 + ((uint32_t)(bc ^ (n & 7)) << 4);
                    ldsm4(t, ba);
                    bh[tl*4 + 2*pp][0]=t[0]; bh[tl*4 + 2*pp][1]=t[1];
                    bh[tl*4 + 2*pp+1][0]=t[2]; bh[tl*4 + 2*pp+1][1]=t[3];
                }
            }
            #pragma unroll
            for (int mt = 0; mt < 2; mt++) {
                float* am = acc + mt * 32;
                #pragma unroll
                for (int u = 0; u < 8; u++) mma_f16(am + 4*u, ah[mt], bh[u]);
            }
        }
        if (kt == KT - 1) {
            #pragma unroll
            for (int mt = 0; mt < 2; mt++) {
                const int r0 = wM + mt * 16 + (l >> 2);
                #pragma unroll
                for (int tl = 0; tl < 2; tl++) {
                    #pragma unroll
                    for (int j = 0; j < 4; j++) {
                        const int col = ng * 256 + tl * 128 + wN + j * 8 + (l & 3) * 2;
                        const float b0 = *(const float*)(sm + BIASOFF + col * 4);
                        const float b1 = *(const float*)(sm + BIASOFF + col * 4 + 4);
                        const int q = mt * 32 + tl * 16 + j * 4;
                        float v00 = acc[q+0] + b0, v01 = acc[q+1] + b1;
                        float v10 = acc[q+2] + b0, v11 = acc[q+3] + b1;
                        v00 = v00 > 0.f ? v00 : expm1f(v00);
                        v01 = v01 > 0.f ? v01 : expm1f(v01);
                        v10 = v10 > 0.f ? v10 : expm1f(v10);
                        v11 = v11 > 0.f ? v11 : expm1f(v11);
                        *(uint32_t*)(out + (base + r0) * N + col)     = packh2(__float2half_rn(v00), __float2half_rn(v01));
                        *(uint32_t*)(out + (base + r0 + 8) * N + col) = packh2(__float2half_rn(v10), __float2half_rn(v11));
                    }
                }
            }
        }
    }
}

// ============================ Layer 4 + fused dot: K=256 -> 64 (W hi/lo) ============================
__global__ void __launch_bounds__(256, 2)
l4_kernel(const __half* __restrict__ in, const float* __restrict__ bias,
          const float* __restrict__ x, float* __restrict__ outv)
{
    extern __shared__ char sm[];
    constexpr int KT = 4;
    const int tid = threadIdx.x, wid = tid >> 5, l = tid & 31;
    const long base = (long)blockIdx.x * 64;
    const uint32_t smb = smem_u32(sm);

    auto prefA = [&](int kt, int buf) {
        const int k0 = kt * 64;
        #pragma unroll
        for (int i = tid; i < 512; i += 256) {
            const int r = i >> 3, c = i & 7;
            const __half* src = in + (base + r) * 256 + k0 + c * 8;
            CP16(smb + buf * 8192 + r * 128 + ((uint32_t)(c ^ (r & 7)) << 4), src);
        }
    };

    #pragma unroll
    for (int i = tid; i < 4096; i += 256) {
        const int plane = i >> 11, j = i & 2047;
        const int n = j >> 5, c = j & 31;
        const __half* src = (plane ? g_Wlo : g_Whi) + 425984 + n * 256 + c * 8;
        CP16(smb + 16384 + plane * 32768 + n * 512 + (((uint32_t)(c ^ (n & 7))) << 4), src);
    }
    prefA(0, 0); CP_COMMIT();
    if (tid < 64) *(float*)(sm + 81920 + tid * 4) = bias[tid];

    const int wM = (wid & 1) * 32, wN = (wid >> 1) * 16;
    const int aRow = wM + (l & 15), aCk = l >> 4;
    const uint32_t aSel = (uint32_t)(aRow & 7);
    const int bnLoc = (l & 7) | ((l & 16) >> 1), bcLoc = (l >> 3) & 1;
    const int sOff = (wid & 1) << 1;

    float acc[16];
    #pragma unroll
    for (int q = 0; q < 16; q++) acc[q] = 0.0f;

    #pragma unroll 1
    for (int kt = 0; kt < KT; ++kt) {
        CP_WAIT0();
        __syncthreads();
        if (kt + 1 < KT) { prefA(kt + 1, (kt + 1) & 1); CP_COMMIT(); }
        const uint32_t ab = smb + (kt & 1) * 8192;
        #pragma unroll
        for (int si = 0; si < 4; si++) {
            const int s = (si + sOff) & 3;
            const int ck = s * 2 + aCk;
            uint32_t ah[2][4];
            #pragma unroll
            for (int mt = 0; mt < 2; mt++)
                ldsm4(ah[mt], ab + (aRow + mt * 16) * 128 + ((uint32_t)(ck ^ aSel) << 4));
            const int bck = kt * 8 + s * 2 + bcLoc;
            uint32_t bh[2][2], bl[2][2], t[4];
            {
                const int n = wN + bnLoc;
                const uint32_t ba = smb + 16384 + n * 512 + ((uint32_t)(bck ^ (n & 7)) << 4);
                ldsm4(t, ba);
                bh[0][0]=t[0]; bh[0][1]=t[1]; bh[1][0]=t[2]; bh[1][1]=t[3];
                ldsm4(t, ba + 32768);
                bl[0][0]=t[0]; bl[0][1]=t[1]; bl[1][0]=t[2]; bl[1][1]=t[3];
            }
            #pragma unroll
            for (int mt = 0; mt < 2; mt++) {
                float* am = acc + mt * 8;
                mma_f16(am + 0, ah[mt], bh[0]);
                mma_f16(am + 4, ah[mt], bh[1]);
            }
            #pragma unroll
            for (int mt = 0; mt < 2; mt++) {
                float* am = acc + mt * 8;
                mma_f16(am + 0, ah[mt], bl[0]);
                mma_f16(am + 4, ah[mt], bl[1]);
            }
        }
    }

    float* zsum = (float*)(sm + 82176);
    #pragma unroll
    for (int mt = 0; mt < 2; mt++) {
        const int r0 = wM + mt * 16 + (l >> 2);
        float p0 = 0.0f, p1 = 0.0f;
        #pragma unroll
        for (int u = 0; u < 2; u++) {
            const int col = wN + u * 8 + (l & 3) * 2;
            const float b0 = *(const float*)(sm + 81920 + col * 4);
            const float b1 = *(const float*)(sm + 81920 + col * 4 + 4);
            const int q = mt * 8 + u * 4;
            const float2 x0 = *(const float2*)(x + (base + r0) * 64 + col);
            const float2 x1 = *(const float2*)(x + (base + r0 + 8) * 64 + col);
            p0 += (acc[q+0] + b0) * x0.x + (acc[q+1] + b1) * x0.y;
            p1 += (acc[q+2] + b0) * x1.x + (acc[q+3] + b1) * x1.y;
        }
        p0 += __shfl_xor_sync(0xFFFFFFFF, p0, 1);
        p0 += __shfl_xor_sync(0xFFFFFFFF, p0, 2);
        p1 += __shfl_xor_sync(0xFFFFFFFF, p1, 1);
        p1 += __shfl_xor_sync(0xFFFFFFFF, p1, 2);
        if ((l & 3) == 0) {
            zsum[r0 * 4 + (wid >> 1)]       = p0;
            zsum[(r0 + 8) * 4 + (wid >> 1)] = p1;
        }
    }
    __syncthreads();
    if (tid < 64) {
        const float s = zsum[tid * 4] + zsum[tid * 4 + 1] + zsum[tid * 4 + 2] + zsum[tid * 4 + 3];
        outv[base + tid] = -s * s;
    }
}

extern "C" void kernel_launch(void* const* d_in, const int* in_sizes, int n_in,
                              void* d_out, int out_size)
{
    const float* x  = (const float*)d_in[0];
    const float* W1 = (const float*)d_in[1];
    const float* b1 = (const float*)d_in[2];
    const float* W2 = (const float*)d_in[3];
    const float* b2 = (const float*)d_in[4];
    const float* W3 = (const float*)d_in[5];
    const float* b3 = (const float*)d_in[6];
    const float* W4 = (const float*)d_in[7];
    const float* b4 = (const float*)d_in[8];
    float* out = (float*)d_out;

    __half *actA, *actB;
    cudaGetSymbolAddress((void**)&actA, g_actA);
    cudaGetSymbolAddress((void**)&actB, g_actB);

    split_all<<<(442368 + 511) / 512, 512>>>(W1, W2, W3, W4);

    constexpr int SZ1 = 75776;   // 8K A + 64K W bufs + 2K bias
    constexpr int SZM5 = 83968;  // 16K A bufs + 64K W bufs + 2K bias
    constexpr int SZM2 = 82944;  // ... + 1K bias
    constexpr int SZ4 = 83200;   // 16K A bufs + 64K W + 256B bias + 1K zsum
    cudaFuncSetAttribute(l1_kernel,       cudaFuncAttributeMaxDynamicSharedMemorySize, SZ1);
    cudaFuncSetAttribute(mid_kernel<512>, cudaFuncAttributeMaxDynamicSharedMemorySize, SZM5);
    cudaFuncSetAttribute(mid_kernel<256>, cudaFuncAttributeMaxDynamicSharedMemorySize, SZM2);
    cudaFuncSetAttribute(l4_kernel,       cudaFuncAttributeMaxDynamicSharedMemorySize, SZ4);

    const int grid = 65536 / 64;  // 1024
    l1_kernel<<<grid, 256, SZ1>>>(x, b1, actA);
    mid_kernel<512><<<grid, 256, SZM5>>>(actA, 32768,  b2, actB);
    mid_kernel<256><<<grid, 256, SZM2>>>(actB, 294912, b3, actA);
    l4_kernel<<<grid, 256, SZ4>>>(actA, b4, x, out);
}

// round 12
// speedup vs baseline: 1.4426x; 1.0228x over previous
#include <cuda_runtime.h>
#include <cuda_fp16.h>
#include <cstdint>

// value[b] = -( x[b] . MLP(x[b]) )^2 — fp16 HMMA GEMM chain.
// R12: compile-time k-chunk order (stagger removed), nested ng/kt loops with
//      kt unroll-2 (compile-time buffer parity) -> fewer ALU issue slots.

__device__ __half g_Whi[442368];
__device__ __half g_Wlo[442368];
__device__ __half g_actA[65536UL * 512];
__device__ __half g_actB[65536UL * 512];

__device__ __forceinline__ uint32_t smem_u32(const void* p) {
    uint32_t a;
    asm("{ .reg .u64 t; cvta.to.shared.u64 t, %1; cvt.u32.u64 %0, t; }" : "=r"(a) : "l"(p));
    return a;
}
__device__ __forceinline__ void ldsm4(uint32_t* r, uint32_t addr) {
    asm volatile("ldmatrix.sync.aligned.m8n8.x4.shared.b16 {%0,%1,%2,%3}, [%4];"
        : "=r"(r[0]), "=r"(r[1]), "=r"(r[2]), "=r"(r[3]) : "r"(addr));
}
__device__ __forceinline__ void mma_f16(float* c, const uint32_t* a, const uint32_t* b) {
    asm volatile("mma.sync.aligned.m16n8k16.row.col.f32.f16.f16.f32 "
        "{%0,%1,%2,%3}, {%4,%5,%6,%7}, {%8,%9}, {%0,%1,%2,%3};"
        : "+f"(c[0]), "+f"(c[1]), "+f"(c[2]), "+f"(c[3])
        : "r"(a[0]), "r"(a[1]), "r"(a[2]), "r"(a[3]), "r"(b[0]), "r"(b[1]));
}
#define CP16(dst, src)  asm volatile("cp.async.cg.shared.global [%0], [%1], 16;" :: "r"(dst), "l"(src))
#define CP_COMMIT()     asm volatile("cp.async.commit_group;" ::: "memory")
#define CP_WAIT0()      asm volatile("cp.async.wait_group 0;" ::: "memory")

__device__ __forceinline__ uint32_t packh2(__half a, __half b) {
    return (uint32_t)__half_as_ushort(a) | ((uint32_t)__half_as_ushort(b) << 16);
}
__device__ __forceinline__ void split1h(float v, __half& h, __half& l) {
    h = __float2half_rn(v);
    l = __float2half_rn(v - __half2float(h));
}

__global__ void split_all(const float* __restrict__ W1, const float* __restrict__ W2,
                          const float* __restrict__ W3, const float* __restrict__ W4) {
    int i = blockIdx.x * blockDim.x + threadIdx.x;
    if (i >= 442368) return;
    float w;
    if (i < 32768)       w = W1[i];
    else if (i < 294912) w = W2[i - 32768];
    else if (i < 425984) w = W3[i - 294912];
    else                 w = W4[i - 425984];
    __half h, l; split1h(w, h, l);
    g_Whi[i] = h; g_Wlo[i] = l;
}

// ============================ Layer 1: x(f32,K=64) -> 512, ELU (W hi/lo) ============================
__global__ void __launch_bounds__(256, 2)
l1_kernel(const float* __restrict__ x, const float* __restrict__ bias,
          __half* __restrict__ out)
{
    extern __shared__ char sm[];
    const int tid = threadIdx.x, wid = tid >> 5, l = tid & 31;
    const long base = (long)blockIdx.x * 64;
    const uint32_t smb = smem_u32(sm);

    auto prefW = [&](int nt, int buf) {
        const int n0 = nt * 128;
        #pragma unroll
        for (int i = tid; i < 2048; i += 256) {
            const int plane = i >> 10, j = i & 1023;
            const int n = j >> 3, c = j & 7;
            const __half* src = (plane ? g_Wlo : g_Whi) + (n0 + n) * 64 + c * 8;
            CP16(smb + 8192 + buf * 32768 + plane * 16384 + n * 128 + ((uint32_t)(c ^ (n & 7)) << 4), src);
        }
    };

    prefW(0, 0); CP_COMMIT();

    #pragma unroll
    for (int i = tid; i < 1024; i += 256) {
        const int r = i >> 4, k4 = (i & 15) * 4;
        const int c = k4 >> 3, wi = (k4 & 4) << 1;
        const float4 v = *(const float4*)(x + (base + r) * 64 + k4);
        const uint32_t off = r * 128 + ((uint32_t)(c ^ (r & 7)) << 4) + wi;
        *(uint32_t*)(sm + off)     = packh2(__float2half_rn(v.x), __float2half_rn(v.y));
        *(uint32_t*)(sm + off + 4) = packh2(__float2half_rn(v.z), __float2half_rn(v.w));
    }
    for (int i = tid; i < 512; i += 256) *(float*)(sm + 73728 + i * 4) = bias[i];

    const int wM = (wid & 1) * 32, wN = (wid >> 1) * 32;
    const int aRow = wM + (l & 15), aCk = l >> 4;
    const uint32_t aSel = (uint32_t)(aRow & 7);
    const int bnLoc = (l & 7) | ((l & 16) >> 1), bcLoc = (l >> 3) & 1;

    #pragma unroll 2
    for (int nt = 0; nt < 4; nt++) {
        CP_WAIT0();
        __syncthreads();
        if (nt + 1 < 4) { prefW(nt + 1, (nt + 1) & 1); CP_COMMIT(); }
        const uint32_t wb = smb + 8192 + (nt & 1) * 32768;

        float acc[32];
        #pragma unroll
        for (int q = 0; q < 32; q++) acc[q] = 0.0f;

        #pragma unroll
        for (int s = 0; s < 4; s++) {
            const int ck = s * 2 + aCk;
            uint32_t ah[2][4];
            #pragma unroll
            for (int mt = 0; mt < 2; mt++)
                ldsm4(ah[mt], smb + (aRow + mt * 16) * 128 + ((uint32_t)(ck ^ aSel) << 4));
            const int bc = s * 2 + bcLoc;
            uint32_t bh[4][2], bl[4][2], t[4];
            #pragma unroll
            for (int pp = 0; pp < 2; pp++) {
                const int n = wN + 16 * pp + bnLoc;
                const uint32_t ba = wb + n * 128 + ((uint32_t)(bc ^ (n & 7)) << 4);
                ldsm4(t, ba);
                bh[2*pp][0]=t[0]; bh[2*pp][1]=t[1]; bh[2*pp+1][0]=t[2]; bh[2*pp+1][1]=t[3];
                ldsm4(t, ba + 16384);
                bl[2*pp][0]=t[0]; bl[2*pp][1]=t[1]; bl[2*pp+1][0]=t[2]; bl[2*pp+1][1]=t[3];
            }
            #pragma unroll
            for (int mt = 0; mt < 2; mt++) {
                float* am = acc + mt * 16;
                #pragma unroll
                for (int u = 0; u < 4; u++) mma_f16(am + 4*u, ah[mt], bh[u]);
                #pragma unroll
                for (int u = 0; u < 4; u++) mma_f16(am + 4*u, ah[mt], bl[u]);
            }
        }
        #pragma unroll
        for (int mt = 0; mt < 2; mt++) {
            const int r0 = wM + mt * 16 + (l >> 2);
            #pragma unroll
            for (int j = 0; j < 4; j++) {
                const int col = nt * 128 + wN + j * 8 + (l & 3) * 2;
                const float b0 = *(const float*)(sm + 73728 + col * 4);
                const float b1 = *(const float*)(sm + 73728 + col * 4 + 4);
                const int q = mt * 16 + j * 4;
                float v00 = acc[q+0] + b0, v01 = acc[q+1] + b1;
                float v10 = acc[q+2] + b0, v11 = acc[q+3] + b1;
                v00 = v00 > 0.f ? v00 : expm1f(v00);
                v01 = v01 > 0.f ? v01 : expm1f(v01);
                v10 = v10 > 0.f ? v10 : expm1f(v10);
                v11 = v11 > 0.f ? v11 : expm1f(v11);
                *(uint32_t*)(out + (base + r0) * 512 + col)     = packh2(__float2half_rn(v00), __float2half_rn(v01));
                *(uint32_t*)(out + (base + r0 + 8) * 512 + col) = packh2(__float2half_rn(v10), __float2half_rn(v11));
            }
        }
    }
}

// ============================ Mid layers: K=512 -> N (ELU), single-fp16 W ============================
// Nested ng/kt loops; kt unrolled x2 so buffer parity and swizzle math fold.
template<int N>
__global__ void __launch_bounds__(256, 2)
mid_kernel(const __half* __restrict__ in, int woff, const float* __restrict__ bias,
           __half* __restrict__ out)
{
    extern __shared__ char sm[];
    constexpr int K = 512, KT = 8, NG = N / 256, NITER = NG * KT;
    constexpr int BIASOFF = 81920;

    const int tid = threadIdx.x, wid = tid >> 5, l = tid & 31;
    const long base = (long)blockIdx.x * 64;
    const uint32_t smb = smem_u32(sm);

    auto prefetch = [&](int it, int buf) {
        const int ng = it >> 3, kt = it & 7;
        const int k0 = kt * 64, n0 = ng * 256;
        #pragma unroll
        for (int i = tid; i < 512; i += 256) {
            const int r = i >> 3, c = i & 7;
            const __half* src = in + (base + r) * K + k0 + c * 8;
            CP16(smb + buf * 8192 + r * 128 + ((uint32_t)(c ^ (r & 7)) << 4), src);
        }
        #pragma unroll
        for (int i = tid; i < 2048; i += 256) {
            const int n = i >> 3, c = i & 7;
            const __half* src = g_Whi + woff + (long)(n0 + n) * K + k0 + c * 8;
            CP16(smb + 16384 + buf * 32768 + n * 128 + ((uint32_t)(c ^ (n & 7)) << 4), src);
        }
    };

    prefetch(0, 0); CP_COMMIT();
    for (int i = tid; i < N; i += 256) *(float*)(sm + BIASOFF + i * 4) = bias[i];

    const int wM = (wid & 1) * 32, wN = (wid >> 1) * 32;
    const int aRow = wM + (l & 15), aCk = l >> 4;
    const uint32_t aSel = (uint32_t)(aRow & 7);
    const int bnLoc = (l & 7) | ((l & 16) >> 1), bcLoc = (l >> 3) & 1;

    float acc[64];

    #pragma unroll 1
    for (int ng = 0; ng < NG; ++ng) {
        #pragma unroll
        for (int q = 0; q < 64; q++) acc[q] = 0.0f;

        #pragma unroll 2
        for (int kt = 0; kt < KT; ++kt) {
            const int it = ng * KT + kt;
            CP_WAIT0();
            __syncthreads();
            if (it + 1 < NITER) { prefetch(it + 1, (kt + 1) & 1); CP_COMMIT(); }
            const uint32_t ab = smb + (kt & 1) * 8192;
            const uint32_t wb = smb + 16384 + (kt & 1) * 32768;
            #pragma unroll
            for (int s = 0; s < 4; s++) {
                const int ck = s * 2 + aCk;
                uint32_t ah[2][4];
                #pragma unroll
                for (int mt = 0; mt < 2; mt++)
                    ldsm4(ah[mt], ab + (aRow + mt * 16) * 128 + ((uint32_t)(ck ^ aSel) << 4));
                const int bc = s * 2 + bcLoc;
                uint32_t bh[8][2], t[4];
                #pragma unroll
                for (int tl = 0; tl < 2; tl++) {
                    #pragma unroll
                    for (int pp = 0; pp < 2; pp++) {
                        const int n = tl * 128 + wN + 16 * pp + bnLoc;
                        const uint32_t ba = wb + n * 128 + ((uint32_t)(bc ^ (n & 7)) << 4);
                        ldsm4(t, ba);
                        bh[tl*4 + 2*pp][0]=t[0]; bh[tl*4 + 2*pp][1]=t[1];
                        bh[tl*4 + 2*pp+1][0]=t[2]; bh[tl*4 + 2*pp+1][1]=t[3];
                    }
                }
                #pragma unroll
                for (int mt = 0; mt < 2; mt++) {
                    float* am = acc + mt * 32;
                    #pragma unroll
                    for (int u = 0; u < 8; u++) mma_f16(am + 4*u, ah[mt], bh[u]);
                }
            }
        }

        // epilogue for this 256-wide n-group
        #pragma unroll
        for (int mt = 0; mt < 2; mt++) {
            const int r0 = wM + mt * 16 + (l >> 2);
            #pragma unroll
            for (int tl = 0; tl < 2; tl++) {
                #pragma unroll
                for (int j = 0; j < 4; j++) {
                    const int col = ng * 256 + tl * 128 + wN + j * 8 + (l & 3) * 2;
                    const float b0 = *(const float*)(sm + BIASOFF + col * 4);
                    const float b1 = *(const float*)(sm + BIASOFF + col * 4 + 4);
                    const int q = mt * 32 + tl * 16 + j * 4;
                    float v00 = acc[q+0] + b0, v01 = acc[q+1] + b1;
                    float v10 = acc[q+2] + b0, v11 = acc[q+3] + b1;
                    v00 = v00 > 0.f ? v00 : expm1f(v00);
                    v01 = v01 > 0.f ? v01 : expm1f(v01);
                    v10 = v10 > 0.f ? v10 : expm1f(v10);
                    v11 = v11 > 0.f ? v11 : expm1f(v11);
                    *(uint32_t*)(out + (base + r0) * N + col)     = packh2(__float2half_rn(v00), __float2half_rn(v01));
                    *(uint32_t*)(out + (base + r0 + 8) * N + col) = packh2(__float2half_rn(v10), __float2half_rn(v11));
                }
            }
        }
    }
}

// ============================ Layer 4 + fused dot: K=256 -> 64 (W hi/lo) ============================
__global__ void __launch_bounds__(256, 2)
l4_kernel(const __half* __restrict__ in, const float* __restrict__ bias,
          const float* __restrict__ x, float* __restrict__ outv)
{
    extern __shared__ char sm[];
    constexpr int KT = 4;
    const int tid = threadIdx.x, wid = tid >> 5, l = tid & 31;
    const long base = (long)blockIdx.x * 64;
    const uint32_t smb = smem_u32(sm);

    auto prefA = [&](int kt, int buf) {
        const int k0 = kt * 64;
        #pragma unroll
        for (int i = tid; i < 512; i += 256) {
            const int r = i >> 3, c = i & 7;
            const __half* src = in + (base + r) * 256 + k0 + c * 8;
            CP16(smb + buf * 8192 + r * 128 + ((uint32_t)(c ^ (r & 7)) << 4), src);
        }
    };

    #pragma unroll
    for (int i = tid; i < 4096; i += 256) {
        const int plane = i >> 11, j = i & 2047;
        const int n = j >> 5, c = j & 31;
        const __half* src = (plane ? g_Wlo : g_Whi) + 425984 + n * 256 + c * 8;
        CP16(smb + 16384 + plane * 32768 + n * 512 + (((uint32_t)(c ^ (n & 7))) << 4), src);
    }
    prefA(0, 0); CP_COMMIT();
    if (tid < 64) *(float*)(sm + 81920 + tid * 4) = bias[tid];

    const int wM = (wid & 1) * 32, wN = (wid >> 1) * 16;
    const int aRow = wM + (l & 15), aCk = l >> 4;
    const uint32_t aSel = (uint32_t)(aRow & 7);
    const int bnLoc = (l & 7) | ((l & 16) >> 1), bcLoc = (l >> 3) & 1;

    float acc[16];
    #pragma unroll
    for (int q = 0; q < 16; q++) acc[q] = 0.0f;

    #pragma unroll 2
    for (int kt = 0; kt < KT; ++kt) {
        CP_WAIT0();
        __syncthreads();
        if (kt + 1 < KT) { prefA(kt + 1, (kt + 1) & 1); CP_COMMIT(); }
        const uint32_t ab = smb + (kt & 1) * 8192;
        #pragma unroll
        for (int s = 0; s < 4; s++) {
            const int ck = s * 2 + aCk;
            uint32_t ah[2][4];
            #pragma unroll
            for (int mt = 0; mt < 2; mt++)
                ldsm4(ah[mt], ab + (aRow + mt * 16) * 128 + ((uint32_t)(ck ^ aSel) << 4));
            const int bck = kt * 8 + s * 2 + bcLoc;
            uint32_t bh[2][2], bl[2][2], t[4];
            {
                const int n = wN + bnLoc;
                const uint32_t ba = smb + 16384 + n * 512 + ((uint32_t)(bck ^ (n & 7)) << 4);
                ldsm4(t, ba);
                bh[0][0]=t[0]; bh[0][1]=t[1]; bh[1][0]=t[2]; bh[1][1]=t[3];
                ldsm4(t, ba + 32768);
                bl[0][0]=t[0]; bl[0][1]=t[1]; bl[1][0]=t[2]; bl[1][1]=t[3];
            }
            #pragma unroll
            for (int mt = 0; mt < 2; mt++) {
                float* am = acc + mt * 8;
                mma_f16(am + 0, ah[mt], bh[0]);
                mma_f16(am + 4, ah[mt], bh[1]);
            }
            #pragma unroll
            for (int mt = 0; mt < 2; mt++) {
                float* am = acc + mt * 8;
                mma_f16(am + 0, ah[mt], bl[0]);
                mma_f16(am + 4, ah[mt], bl[1]);
            }
        }
    }

    float* zsum = (float*)(sm + 82176);
    #pragma unroll
    for (int mt = 0; mt < 2; mt++) {
        const int r0 = wM + mt * 16 + (l >> 2);
        float p0 = 0.0f, p1 = 0.0f;
        #pragma unroll
        for (int u = 0; u < 2; u++) {
            const int col = wN + u * 8 + (l & 3) * 2;
            const float b0 = *(const float*)(sm + 81920 + col * 4);
            const float b1 = *(const float*)(sm + 81920 + col * 4 + 4);
            const int q = mt * 8 + u * 4;
            const float2 x0 = *(const float2*)(x + (base + r0) * 64 + col);
            const float2 x1 = *(const float2*)(x + (base + r0 + 8) * 64 + col);
            p0 += (acc[q+0] + b0) * x0.x + (acc[q+1] + b1) * x0.y;
            p1 += (acc[q+2] + b0) * x1.x + (acc[q+3] + b1) * x1.y;
        }
        p0 += __shfl_xor_sync(0xFFFFFFFF, p0, 1);
        p0 += __shfl_xor_sync(0xFFFFFFFF, p0, 2);
        p1 += __shfl_xor_sync(0xFFFFFFFF, p1, 1);
        p1 += __shfl_xor_sync(0xFFFFFFFF, p1, 2);
        if ((l & 3) == 0) {
            zsum[r0 * 4 + (wid >> 1)]       = p0;
            zsum[(r0 + 8) * 4 + (wid >> 1)] = p1;
        }
    }
    __syncthreads();
    if (tid < 64) {
        const float s = zsum[tid * 4] + zsum[tid * 4 + 1] + zsum[tid * 4 + 2] + zsum[tid * 4 + 3];
        outv[base + tid] = -s * s;
    }
}

extern "C" void kernel_launch(void* const* d_in, const int* in_sizes, int n_in,
                              void* d_out, int out_size)
{
    const float* x  = (const float*)d_in[0];
    const float* W1 = (const float*)d_in[1];
    const float* b1 = (const float*)d_in[2];
    const float* W2 = (const float*)d_in[3];
    const float* b2 = (const float*)d_in[4];
    const float* W3 = (const float*)d_in[5];
    const float* b3 = (const float*)d_in[6];
    const float* W4 = (const float*)d_in[7];
    const float* b4 = (const float*)d_in[8];
    float* out = (float*)d_out;

    __half *actA, *actB;
    cudaGetSymbolAddress((void**)&actA, g_actA);
    cudaGetSymbolAddress((void**)&actB, g_actB);

    split_all<<<(442368 + 511) / 512, 512>>>(W1, W2, W3, W4);

    constexpr int SZ1 = 75776;
    constexpr int SZM5 = 83968;
    constexpr int SZM2 = 82944;
    constexpr int SZ4 = 83200;
    cudaFuncSetAttribute(l1_kernel,       cudaFuncAttributeMaxDynamicSharedMemorySize, SZ1);
    cudaFuncSetAttribute(mid_kernel<512>, cudaFuncAttributeMaxDynamicSharedMemorySize, SZM5);
    cudaFuncSetAttribute(mid_kernel<256>, cudaFuncAttributeMaxDynamicSharedMemorySize, SZM2);
    cudaFuncSetAttribute(l4_kernel,       cudaFuncAttributeMaxDynamicSharedMemorySize, SZ4);

    const int grid = 65536 / 64;  // 1024
    l1_kernel<<<grid, 256, SZ1>>>(x, b1, actA);
    mid_kernel<512><<<grid, 256, SZM5>>>(actA, 32768,  b2, actB);
    mid_kernel<256><<<grid, 256, SZM2>>>(actB, 294912, b3, actA);
    l4_kernel<<<grid, 256, SZ4>>>(actA, b4, x, out);
}

// round 13
// speedup vs baseline: 1.4629x; 1.0141x over previous
#include <cuda_runtime.h>
#include <cuda_fp16.h>
#include <cstdint>

// value[b] = -( x[b] . MLP(x[b]) )^2 — fp16 HMMA GEMM chain.
// R13: L3+L4 fused into one kernel (act3 lives in smem, W4 hi/lo streamed
//      through the A-buffers) -> one fewer launch + no act3 gmem round-trip.

__device__ __half g_Whi[442368];
__device__ __half g_Wlo[442368];
__device__ __half g_actA[65536UL * 512];
__device__ __half g_actB[65536UL * 512];

__device__ __forceinline__ uint32_t smem_u32(const void* p) {
    uint32_t a;
    asm("{ .reg .u64 t; cvta.to.shared.u64 t, %1; cvt.u32.u64 %0, t; }" : "=r"(a) : "l"(p));
    return a;
}
__device__ __forceinline__ void ldsm4(uint32_t* r, uint32_t addr) {
    asm volatile("ldmatrix.sync.aligned.m8n8.x4.shared.b16 {%0,%1,%2,%3}, [%4];"
        : "=r"(r[0]), "=r"(r[1]), "=r"(r[2]), "=r"(r[3]) : "r"(addr));
}
__device__ __forceinline__ void mma_f16(float* c, const uint32_t* a, const uint32_t* b) {
    asm volatile("mma.sync.aligned.m16n8k16.row.col.f32.f16.f16.f32 "
        "{%0,%1,%2,%3}, {%4,%5,%6,%7}, {%8,%9}, {%0,%1,%2,%3};"
        : "+f"(c[0]), "+f"(c[1]), "+f"(c[2]), "+f"(c[3])
        : "r"(a[0]), "r"(a[1]), "r"(a[2]), "r"(a[3]), "r"(b[0]), "r"(b[1]));
}
#define CP16(dst, src)  asm volatile("cp.async.cg.shared.global [%0], [%1], 16;" :: "r"(dst), "l"(src))
#define CP_COMMIT()     asm volatile("cp.async.commit_group;" ::: "memory")
#define CP_WAIT0()      asm volatile("cp.async.wait_group 0;" ::: "memory")

__device__ __forceinline__ uint32_t packh2(__half a, __half b) {
    return (uint32_t)__half_as_ushort(a) | ((uint32_t)__half_as_ushort(b) << 16);
}
__device__ __forceinline__ void split1h(float v, __half& h, __half& l) {
    h = __float2half_rn(v);
    l = __float2half_rn(v - __half2float(h));
}

__global__ void split_all(const float* __restrict__ W1, const float* __restrict__ W2,
                          const float* __restrict__ W3, const float* __restrict__ W4) {
    int i = blockIdx.x * blockDim.x + threadIdx.x;
    if (i >= 442368) return;
    float w;
    if (i < 32768)       w = W1[i];
    else if (i < 294912) w = W2[i - 32768];
    else if (i < 425984) w = W3[i - 294912];
    else                 w = W4[i - 425984];
    __half h, l; split1h(w, h, l);
    g_Whi[i] = h; g_Wlo[i] = l;
}

// ============================ Layer 1: x(f32,K=64) -> 512, ELU (W hi/lo) ============================
__global__ void __launch_bounds__(256, 2)
l1_kernel(const float* __restrict__ x, const float* __restrict__ bias,
          __half* __restrict__ out)
{
    extern __shared__ char sm[];
    const int tid = threadIdx.x, wid = tid >> 5, l = tid & 31;
    const long base = (long)blockIdx.x * 64;
    const uint32_t smb = smem_u32(sm);

    auto prefW = [&](int nt, int buf) {
        const int n0 = nt * 128;
        #pragma unroll
        for (int i = tid; i < 2048; i += 256) {
            const int plane = i >> 10, j = i & 1023;
            const int n = j >> 3, c = j & 7;
            const __half* src = (plane ? g_Wlo : g_Whi) + (n0 + n) * 64 + c * 8;
            CP16(smb + 8192 + buf * 32768 + plane * 16384 + n * 128 + ((uint32_t)(c ^ (n & 7)) << 4), src);
        }
    };

    prefW(0, 0); CP_COMMIT();

    #pragma unroll
    for (int i = tid; i < 1024; i += 256) {
        const int r = i >> 4, k4 = (i & 15) * 4;
        const int c = k4 >> 3, wi = (k4 & 4) << 1;
        const float4 v = *(const float4*)(x + (base + r) * 64 + k4);
        const uint32_t off = r * 128 + ((uint32_t)(c ^ (r & 7)) << 4) + wi;
        *(uint32_t*)(sm + off)     = packh2(__float2half_rn(v.x), __float2half_rn(v.y));
        *(uint32_t*)(sm + off + 4) = packh2(__float2half_rn(v.z), __float2half_rn(v.w));
    }
    for (int i = tid; i < 512; i += 256) *(float*)(sm + 73728 + i * 4) = bias[i];

    const int wM = (wid & 1) * 32, wN = (wid >> 1) * 32;
    const int aRow = wM + (l & 15), aCk = l >> 4;
    const uint32_t aSel = (uint32_t)(aRow & 7);
    const int bnLoc = (l & 7) | ((l & 16) >> 1), bcLoc = (l >> 3) & 1;

    #pragma unroll 2
    for (int nt = 0; nt < 4; nt++) {
        CP_WAIT0();
        __syncthreads();
        if (nt + 1 < 4) { prefW(nt + 1, (nt + 1) & 1); CP_COMMIT(); }
        const uint32_t wb = smb + 8192 + (nt & 1) * 32768;

        float acc[32];
        #pragma unroll
        for (int q = 0; q < 32; q++) acc[q] = 0.0f;

        #pragma unroll
        for (int s = 0; s < 4; s++) {
            const int ck = s * 2 + aCk;
            uint32_t ah[2][4];
            #pragma unroll
            for (int mt = 0; mt < 2; mt++)
                ldsm4(ah[mt], smb + (aRow + mt * 16) * 128 + ((uint32_t)(ck ^ aSel) << 4));
            const int bc = s * 2 + bcLoc;
            uint32_t bh[4][2], bl[4][2], t[4];
            #pragma unroll
            for (int pp = 0; pp < 2; pp++) {
                const int n = wN + 16 * pp + bnLoc;
                const uint32_t ba = wb + n * 128 + ((uint32_t)(bc ^ (n & 7)) << 4);
                ldsm4(t, ba);
                bh[2*pp][0]=t[0]; bh[2*pp][1]=t[1]; bh[2*pp+1][0]=t[2]; bh[2*pp+1][1]=t[3];
                ldsm4(t, ba + 16384);
                bl[2*pp][0]=t[0]; bl[2*pp][1]=t[1]; bl[2*pp+1][0]=t[2]; bl[2*pp+1][1]=t[3];
            }
            #pragma unroll
            for (int mt = 0; mt < 2; mt++) {
                float* am = acc + mt * 16;
                #pragma unroll
                for (int u = 0; u < 4; u++) mma_f16(am + 4*u, ah[mt], bh[u]);
                #pragma unroll
                for (int u = 0; u < 4; u++) mma_f16(am + 4*u, ah[mt], bl[u]);
            }
        }
        #pragma unroll
        for (int mt = 0; mt < 2; mt++) {
            const int r0 = wM + mt * 16 + (l >> 2);
            #pragma unroll
            for (int j = 0; j < 4; j++) {
                const int col = nt * 128 + wN + j * 8 + (l & 3) * 2;
                const float b0 = *(const float*)(sm + 73728 + col * 4);
                const float b1 = *(const float*)(sm + 73728 + col * 4 + 4);
                const int q = mt * 16 + j * 4;
                float v00 = acc[q+0] + b0, v01 = acc[q+1] + b1;
                float v10 = acc[q+2] + b0, v11 = acc[q+3] + b1;
                v00 = v00 > 0.f ? v00 : expm1f(v00);
                v01 = v01 > 0.f ? v01 : expm1f(v01);
                v10 = v10 > 0.f ? v10 : expm1f(v10);
                v11 = v11 > 0.f ? v11 : expm1f(v11);
                *(uint32_t*)(out + (base + r0) * 512 + col)     = packh2(__float2half_rn(v00), __float2half_rn(v01));
                *(uint32_t*)(out + (base + r0 + 8) * 512 + col) = packh2(__float2half_rn(v10), __float2half_rn(v11));
            }
        }
    }
}

// ============================ Layer 2: K=512 -> 512 (ELU), single-fp16 W ============================
__global__ void __launch_bounds__(256, 2)
mid512_kernel(const __half* __restrict__ in, const float* __restrict__ bias,
              __half* __restrict__ out)
{
    extern __shared__ char sm[];
    constexpr int K = 512, KT = 8, NG = 2, NITER = NG * KT, WOFF = 32768;
    constexpr int BIASOFF = 81920;

    const int tid = threadIdx.x, wid = tid >> 5, l = tid & 31;
    const long base = (long)blockIdx.x * 64;
    const uint32_t smb = smem_u32(sm);

    auto prefetch = [&](int it, int buf) {
        const int ng = it >> 3, kt = it & 7;
        const int k0 = kt * 64, n0 = ng * 256;
        #pragma unroll
        for (int i = tid; i < 512; i += 256) {
            const int r = i >> 3, c = i & 7;
            const __half* src = in + (base + r) * K + k0 + c * 8;
            CP16(smb + buf * 8192 + r * 128 + ((uint32_t)(c ^ (r & 7)) << 4), src);
        }
        #pragma unroll
        for (int i = tid; i < 2048; i += 256) {
            const int n = i >> 3, c = i & 7;
            const __half* src = g_Whi + WOFF + (long)(n0 + n) * K + k0 + c * 8;
            CP16(smb + 16384 + buf * 32768 + n * 128 + ((uint32_t)(c ^ (n & 7)) << 4), src);
        }
    };

    prefetch(0, 0); CP_COMMIT();
    for (int i = tid; i < 512; i += 256) *(float*)(sm + BIASOFF + i * 4) = bias[i];

    const int wM = (wid & 1) * 32, wN = (wid >> 1) * 32;
    const int aRow = wM + (l & 15), aCk = l >> 4;
    const uint32_t aSel = (uint32_t)(aRow & 7);
    const int bnLoc = (l & 7) | ((l & 16) >> 1), bcLoc = (l >> 3) & 1;

    float acc[64];

    #pragma unroll 1
    for (int ng = 0; ng < NG; ++ng) {
        #pragma unroll
        for (int q = 0; q < 64; q++) acc[q] = 0.0f;

        #pragma unroll 2
        for (int kt = 0; kt < KT; ++kt) {
            const int it = ng * KT + kt;
            CP_WAIT0();
            __syncthreads();
            if (it + 1 < NITER) { prefetch(it + 1, (kt + 1) & 1); CP_COMMIT(); }
            const uint32_t ab = smb + (kt & 1) * 8192;
            const uint32_t wb = smb + 16384 + (kt & 1) * 32768;
            #pragma unroll
            for (int s = 0; s < 4; s++) {
                const int ck = s * 2 + aCk;
                uint32_t ah[2][4];
                #pragma unroll
                for (int mt = 0; mt < 2; mt++)
                    ldsm4(ah[mt], ab + (aRow + mt * 16) * 128 + ((uint32_t)(ck ^ aSel) << 4));
                const int bc = s * 2 + bcLoc;
                uint32_t bh[8][2], t[4];
                #pragma unroll
                for (int tl = 0; tl < 2; tl++) {
                    #pragma unroll
                    for (int pp = 0; pp < 2; pp++) {
                        const int n = tl * 128 + wN + 16 * pp + bnLoc;
                        const uint32_t ba = wb + n * 128 + ((uint32_t)(bc ^ (n & 7)) << 4);
                        ldsm4(t, ba);
                        bh[tl*4 + 2*pp][0]=t[0]; bh[tl*4 + 2*pp][1]=t[1];
                        bh[tl*4 + 2*pp+1][0]=t[2]; bh[tl*4 + 2*pp+1][1]=t[3];
                    }
                }
                #pragma unroll
                for (int mt = 0; mt < 2; mt++) {
                    float* am = acc + mt * 32;
                    #pragma unroll
                    for (int u = 0; u < 8; u++) mma_f16(am + 4*u, ah[mt], bh[u]);
                }
            }
        }
        #pragma unroll
        for (int mt = 0; mt < 2; mt++) {
            const int r0 = wM + mt * 16 + (l >> 2);
            #pragma unroll
            for (int tl = 0; tl < 2; tl++) {
                #pragma unroll
                for (int j = 0; j < 4; j++) {
                    const int col = ng * 256 + tl * 128 + wN + j * 8 + (l & 3) * 2;
                    const float b0 = *(const float*)(sm + BIASOFF + col * 4);
                    const float b1 = *(const float*)(sm + BIASOFF + col * 4 + 4);
                    const int q = mt * 32 + tl * 16 + j * 4;
                    float v00 = acc[q+0] + b0, v01 = acc[q+1] + b1;
                    float v10 = acc[q+2] + b0, v11 = acc[q+3] + b1;
                    v00 = v00 > 0.f ? v00 : expm1f(v00);
                    v01 = v01 > 0.f ? v01 : expm1f(v01);
                    v10 = v10 > 0.f ? v10 : expm1f(v10);
                    v11 = v11 > 0.f ? v11 : expm1f(v11);
                    *(uint32_t*)(out + (base + r0) * 512 + col)     = packh2(__float2half_rn(v00), __float2half_rn(v01));
                    *(uint32_t*)(out + (base + r0 + 8) * 512 + col) = packh2(__float2half_rn(v10), __float2half_rn(v11));
                }
            }
        }
    }
}

// ============================ Fused L3+L4: K=512 -> 256 (ELU) -> 64 -> -(x.z)^2 ============================
// smem: [0,16384) A/W4 bufs 2x8K | [16384,81920) W3 bufs 2x32K (act3 reuses buf0)
//       [81920,82944) bias3 | [82944,83200) bias4 | [83200,84224) zsum
__global__ void __launch_bounds__(256, 2)
l34_kernel(const __half* __restrict__ in, const float* __restrict__ bias3,
           const float* __restrict__ bias4, const float* __restrict__ x,
           float* __restrict__ outv)
{
    extern __shared__ char sm[];
    constexpr int K = 512, KT = 8, WOFF3 = 294912, WOFF4 = 425984;
    constexpr int ACT3 = 16384, BIAS3 = 81920, BIAS4 = 82944, ZSUM = 83200;

    const int tid = threadIdx.x, wid = tid >> 5, l = tid & 31;
    const long base = (long)blockIdx.x * 64;
    const uint32_t smb = smem_u32(sm);

    auto prefetch = [&](int it, int buf) {
        const int kt = it & 7;
        const int k0 = kt * 64;
        #pragma unroll
        for (int i = tid; i < 512; i += 256) {
            const int r = i >> 3, c = i & 7;
            const __half* src = in + (base + r) * K + k0 + c * 8;
            CP16(smb + buf * 8192 + r * 128 + ((uint32_t)(c ^ (r & 7)) << 4), src);
        }
        #pragma unroll
        for (int i = tid; i < 2048; i += 256) {
            const int n = i >> 3, c = i & 7;
            const __half* src = g_Whi + WOFF3 + (long)n * K + k0 + c * 8;
            CP16(smb + 16384 + buf * 32768 + n * 128 + ((uint32_t)(c ^ (n & 7)) << 4), src);
        }
    };

    prefetch(0, 0); CP_COMMIT();
    for (int i = tid; i < 256; i += 256) *(float*)(sm + BIAS3 + i * 4) = bias3[i];
    if (tid < 64) *(float*)(sm + BIAS4 + tid * 4) = bias4[tid];

    const int wM = (wid & 1) * 32, wN = (wid >> 1) * 32;
    const int aRow = wM + (l & 15), aCk = l >> 4;
    const uint32_t aSel = (uint32_t)(aRow & 7);
    const int bnLoc = (l & 7) | ((l & 16) >> 1), bcLoc = (l >> 3) & 1;

    // ---- L3 GEMM: acc[64] over N=256 ----
    float acc[64];
    #pragma unroll
    for (int q = 0; q < 64; q++) acc[q] = 0.0f;

    #pragma unroll 2
    for (int kt = 0; kt < KT; ++kt) {
        CP_WAIT0();
        __syncthreads();
        if (kt + 1 < KT) { prefetch(kt + 1, (kt + 1) & 1); CP_COMMIT(); }
        const uint32_t ab = smb + (kt & 1) * 8192;
        const uint32_t wb = smb + 16384 + (kt & 1) * 32768;
        #pragma unroll
        for (int s = 0; s < 4; s++) {
            const int ck = s * 2 + aCk;
            uint32_t ah[2][4];
            #pragma unroll
            for (int mt = 0; mt < 2; mt++)
                ldsm4(ah[mt], ab + (aRow + mt * 16) * 128 + ((uint32_t)(ck ^ aSel) << 4));
            const int bc = s * 2 + bcLoc;
            uint32_t bh[8][2], t[4];
            #pragma unroll
            for (int tl = 0; tl < 2; tl++) {
                #pragma unroll
                for (int pp = 0; pp < 2; pp++) {
                    const int n = tl * 128 + wN + 16 * pp + bnLoc;
                    const uint32_t ba = wb + n * 128 + ((uint32_t)(bc ^ (n & 7)) << 4);
                    ldsm4(t, ba);
                    bh[tl*4 + 2*pp][0]=t[0]; bh[tl*4 + 2*pp][1]=t[1];
                    bh[tl*4 + 2*pp+1][0]=t[2]; bh[tl*4 + 2*pp+1][1]=t[3];
                }
            }
            #pragma unroll
            for (int mt = 0; mt < 2; mt++) {
                float* am = acc + mt * 32;
                #pragma unroll
                for (int u = 0; u < 8; u++) mma_f16(am + 4*u, ah[mt], bh[u]);
            }
        }
    }

    // ---- act3 (bias+ELU) -> smem at ACT3 (row stride 512B, 16B-chunk swizzle) ----
    #pragma unroll
    for (int mt = 0; mt < 2; mt++) {
        const int r0 = wM + mt * 16 + (l >> 2);
        #pragma unroll
        for (int tl = 0; tl < 2; tl++) {
            #pragma unroll
            for (int j = 0; j < 4; j++) {
                const int col = tl * 128 + wN + j * 8 + (l & 3) * 2;
                const float b0 = *(const float*)(sm + BIAS3 + col * 4);
                const float b1 = *(const float*)(sm + BIAS3 + col * 4 + 4);
                const int q = mt * 32 + tl * 16 + j * 4;
                float v00 = acc[q+0] + b0, v01 = acc[q+1] + b1;
                float v10 = acc[q+2] + b0, v11 = acc[q+3] + b1;
                v00 = v00 > 0.f ? v00 : expm1f(v00);
                v01 = v01 > 0.f ? v01 : expm1f(v01);
                v10 = v10 > 0.f ? v10 : expm1f(v10);
                v11 = v11 > 0.f ? v11 : expm1f(v11);
                const int c16 = col >> 3;
                const int wi = (col & 7) * 2;
                const uint32_t a0 = ACT3 + r0 * 512 + ((uint32_t)(c16 ^ (r0 & 7)) << 4) + wi;
                const uint32_t a1 = ACT3 + (r0 + 8) * 512 + ((uint32_t)(c16 ^ ((r0 + 8) & 7)) << 4) + wi;
                *(uint32_t*)(sm + a0) = packh2(__float2half_rn(v00), __float2half_rn(v01));
                *(uint32_t*)(sm + a1) = packh2(__float2half_rn(v10), __float2half_rn(v11));
            }
        }
    }
    __syncthreads();

    // ---- L4 GEMM: z[64] = act3 . W4^T (+b4), W4 hi/lo streamed in 4 chunks ----
    const int wN4 = (wid >> 1) * 16;
    float acc4[16];
    #pragma unroll
    for (int q = 0; q < 16; q++) acc4[q] = 0.0f;

    #pragma unroll 1
    for (int kc = 0; kc < 4; ++kc) {
        // load W4 chunk: 64 n-rows x 8 16B-chunks x 2 planes (hi at buf0, lo at buf1)
        #pragma unroll
        for (int i = tid; i < 1024; i += 256) {
            const int plane = i >> 9, j = i & 511;
            const int n = j >> 3, c = j & 7;
            const __half* src = (plane ? g_Wlo : g_Whi) + WOFF4 + n * 256 + kc * 64 + c * 8;
            CP16(smb + plane * 8192 + n * 128 + ((uint32_t)(c ^ (n & 7)) << 4), src);
        }
        CP_COMMIT(); CP_WAIT0();
        __syncthreads();
        #pragma unroll
        for (int s = 0; s < 4; s++) {
            const int ckk = kc * 8 + s * 2 + aCk;
            uint32_t ah[2][4];
            #pragma unroll
            for (int mt = 0; mt < 2; mt++)
                ldsm4(ah[mt], smb + ACT3 + (aRow + mt * 16) * 512 + ((uint32_t)(ckk ^ aSel) << 4));
            const int bc = s * 2 + bcLoc;
            uint32_t bh[2][2], bl[2][2], t[4];
            {
                const int n = wN4 + bnLoc;
                const uint32_t ba = smb + n * 128 + ((uint32_t)(bc ^ (n & 7)) << 4);
                ldsm4(t, ba);
                bh[0][0]=t[0]; bh[0][1]=t[1]; bh[1][0]=t[2]; bh[1][1]=t[3];
                ldsm4(t, ba + 8192);
                bl[0][0]=t[0]; bl[0][1]=t[1]; bl[1][0]=t[2]; bl[1][1]=t[3];
            }
            #pragma unroll
            for (int mt = 0; mt < 2; mt++) {
                float* am = acc4 + mt * 8;
                mma_f16(am + 0, ah[mt], bh[0]);
                mma_f16(am + 4, ah[mt], bh[1]);
                mma_f16(am + 0, ah[mt], bl[0]);
                mma_f16(am + 4, ah[mt], bl[1]);
            }
        }
        __syncthreads();
    }

    // ---- fused dot: out = -(x . z)^2 ----
    float* zsum = (float*)(sm + ZSUM);
    #pragma unroll
    for (int mt = 0; mt < 2; mt++) {
        const int r0 = wM + mt * 16 + (l >> 2);
        float p0 = 0.0f, p1 = 0.0f;
        #pragma unroll
        for (int u = 0; u < 2; u++) {
            const int col = wN4 + u * 8 + (l & 3) * 2;
            const float b0 = *(const float*)(sm + BIAS4 + col * 4);
            const float b1 = *(const float*)(sm + BIAS4 + col * 4 + 4);
            const int q = mt * 8 + u * 4;
            const float2 x0 = *(const float2*)(x + (base + r0) * 64 + col);
            const float2 x1 = *(const float2*)(x + (base + r0 + 8) * 64 + col);
            p0 += (acc4[q+0] + b0) * x0.x + (acc4[q+1] + b1) * x0.y;
            p1 += (acc4[q+2] + b0) * x1.x + (acc4[q+3] + b1) * x1.y;
        }
        p0 += __shfl_xor_sync(0xFFFFFFFF, p0, 1);
        p0 += __shfl_xor_sync(0xFFFFFFFF, p0, 2);
        p1 += __shfl_xor_sync(0xFFFFFFFF, p1, 1);
        p1 += __shfl_xor_sync(0xFFFFFFFF, p1, 2);
        if ((l & 3) == 0) {
            zsum[r0 * 4 + (wid >> 1)]       = p0;
            zsum[(r0 + 8) * 4 + (wid >> 1)] = p1;
        }
    }
    __syncthreads();
    if (tid < 64) {
        const float s = zsum[tid * 4] + zsum[tid * 4 + 1] + zsum[tid * 4 + 2] + zsum[tid * 4 + 3];
        outv[base + tid] = -s * s;
    }
}

extern "C" void kernel_launch(void* const* d_in, const int* in_sizes, int n_in,
                              void* d_out, int out_size)
{
    const float* x  = (const float*)d_in[0];
    const float* W1 = (const float*)d_in[1];
    const float* b1 = (const float*)d_in[2];
    const float* W2 = (const float*)d_in[3];
    const float* b2 = (const float*)d_in[4];
    const float* W3 = (const float*)d_in[5];
    const float* b3 = (const float*)d_in[6];
    const float* W4 = (const float*)d_in[7];
    const float* b4 = (const float*)d_in[8];
    float* out = (float*)d_out;

    __half *actA, *actB;
    cudaGetSymbolAddress((void**)&actA, g_actA);
    cudaGetSymbolAddress((void**)&actB, g_actB);

    split_all<<<(442368 + 511) / 512, 512>>>(W1, W2, W3, W4);

    constexpr int SZ1 = 75776;
    constexpr int SZM5 = 83968;
    constexpr int SZ34 = 84224;
    cudaFuncSetAttribute(l1_kernel,     cudaFuncAttributeMaxDynamicSharedMemorySize, SZ1);
    cudaFuncSetAttribute(mid512_kernel, cudaFuncAttributeMaxDynamicSharedMemorySize, SZM5);
    cudaFuncSetAttribute(l34_kernel,    cudaFuncAttributeMaxDynamicSharedMemorySize, SZ34);

    const int grid = 65536 / 64;  // 1024
    l1_kernel<<<grid, 256, SZ1>>>(x, b1, actA);
    mid512_kernel<<<grid, 256, SZM5>>>(actA, b2, actB);
    l34_kernel<<<grid, 256, SZ34>>>(actB, b3, b4, x, out);
}

// round 14
// speedup vs baseline: 1.4951x; 1.0220x over previous
#include <cuda_runtime.h>
#include <cuda_fp16.h>
#include <cstdint>

// value[b] = -( x[b] . MLP(x[b]) )^2 — fp16 HMMA GEMM chain.
// R14: strength-reduced prefetch addressing — per-thread base pointers
//      precomputed once (swizzle is j-invariant since 32j % 8 == 0),
//      each cp.async = base + compile-time offset. Arithmetic unchanged.

__device__ __half g_Whi[442368];
__device__ __half g_Wlo[442368];
__device__ __half g_actA[65536UL * 512];
__device__ __half g_actB[65536UL * 512];

__device__ __forceinline__ uint32_t smem_u32(const void* p) {
    uint32_t a;
    asm("{ .reg .u64 t; cvta.to.shared.u64 t, %1; cvt.u32.u64 %0, t; }" : "=r"(a) : "l"(p));
    return a;
}
__device__ __forceinline__ void ldsm4(uint32_t* r, uint32_t addr) {
    asm volatile("ldmatrix.sync.aligned.m8n8.x4.shared.b16 {%0,%1,%2,%3}, [%4];"
        : "=r"(r[0]), "=r"(r[1]), "=r"(r[2]), "=r"(r[3]) : "r"(addr));
}
__device__ __forceinline__ void mma_f16(float* c, const uint32_t* a, const uint32_t* b) {
    asm volatile("mma.sync.aligned.m16n8k16.row.col.f32.f16.f16.f32 "
        "{%0,%1,%2,%3}, {%4,%5,%6,%7}, {%8,%9}, {%0,%1,%2,%3};"
        : "+f"(c[0]), "+f"(c[1]), "+f"(c[2]), "+f"(c[3])
        : "r"(a[0]), "r"(a[1]), "r"(a[2]), "r"(a[3]), "r"(b[0]), "r"(b[1]));
}
#define CP16(dst, src)  asm volatile("cp.async.cg.shared.global [%0], [%1], 16;" :: "r"(dst), "l"(src))
#define CP_COMMIT()     asm volatile("cp.async.commit_group;" ::: "memory")
#define CP_WAIT0()      asm volatile("cp.async.wait_group 0;" ::: "memory")

__device__ __forceinline__ uint32_t packh2(__half a, __half b) {
    return (uint32_t)__half_as_ushort(a) | ((uint32_t)__half_as_ushort(b) << 16);
}
__device__ __forceinline__ void split1h(float v, __half& h, __half& l) {
    h = __float2half_rn(v);
    l = __float2half_rn(v - __half2float(h));
}

__global__ void split_all(const float* __restrict__ W1, const float* __restrict__ W2,
                          const float* __restrict__ W3, const float* __restrict__ W4) {
    int i = blockIdx.x * blockDim.x + threadIdx.x;
    if (i >= 442368) return;
    float w;
    if (i < 32768)       w = W1[i];
    else if (i < 294912) w = W2[i - 32768];
    else if (i < 425984) w = W3[i - 294912];
    else                 w = W4[i - 425984];
    __half h, l; split1h(w, h, l);
    g_Whi[i] = h; g_Wlo[i] = l;
}

// ============================ Layer 1: x(f32,K=64) -> 512, ELU (W hi/lo) ============================
__global__ void __launch_bounds__(256, 2)
l1_kernel(const float* __restrict__ x, const float* __restrict__ bias,
          __half* __restrict__ out)
{
    extern __shared__ char sm[];
    const int tid = threadIdx.x, wid = tid >> 5, l = tid & 31;
    const long base = (long)blockIdx.x * 64;
    const uint32_t smb = smem_u32(sm);

    // per-thread prefetch bases (pr = row-group, pc = 16B-chunk)
    const int pr = tid >> 3, pc = tid & 7;
    const uint32_t swz = ((uint32_t)(pc ^ (pr & 7)) << 4);
    const __half* wSh = g_Whi + pr * 64 + pc * 8;   // + nt*8192 + jj*2048
    const __half* wSl = g_Wlo + pr * 64 + pc * 8;
    const uint32_t wD1 = smb + 8192 + pr * 128 + swz;  // + buf*32768 + plane*16384 + jj*4096

    auto prefW = [&](int nt, int buf) {
        const int so = nt * 8192;
        const uint32_t wd = wD1 + buf * 32768;
        #pragma unroll
        for (int jj = 0; jj < 4; jj++) {
            CP16(wd + jj * 4096,         wSh + so + jj * 2048);
            CP16(wd + 16384 + jj * 4096, wSl + so + jj * 2048);
        }
    };

    prefW(0, 0); CP_COMMIT();

    #pragma unroll
    for (int i = tid; i < 1024; i += 256) {
        const int r = i >> 4, k4 = (i & 15) * 4;
        const int c = k4 >> 3, wi = (k4 & 4) << 1;
        const float4 v = *(const float4*)(x + (base + r) * 64 + k4);
        const uint32_t off = r * 128 + ((uint32_t)(c ^ (r & 7)) << 4) + wi;
        *(uint32_t*)(sm + off)     = packh2(__float2half_rn(v.x), __float2half_rn(v.y));
        *(uint32_t*)(sm + off + 4) = packh2(__float2half_rn(v.z), __float2half_rn(v.w));
    }
    for (int i = tid; i < 512; i += 256) *(float*)(sm + 73728 + i * 4) = bias[i];

    const int wM = (wid & 1) * 32, wN = (wid >> 1) * 32;
    const int aRow = wM + (l & 15), aCk = l >> 4;
    const uint32_t aSel = (uint32_t)(aRow & 7);
    const int bnLoc = (l & 7) | ((l & 16) >> 1), bcLoc = (l >> 3) & 1;

    #pragma unroll 2
    for (int nt = 0; nt < 4; nt++) {
        CP_WAIT0();
        __syncthreads();
        if (nt + 1 < 4) { prefW(nt + 1, (nt + 1) & 1); CP_COMMIT(); }
        const uint32_t wb = smb + 8192 + (nt & 1) * 32768;

        float acc[32];
        #pragma unroll
        for (int q = 0; q < 32; q++) acc[q] = 0.0f;

        #pragma unroll
        for (int s = 0; s < 4; s++) {
            const int ck = s * 2 + aCk;
            uint32_t ah[2][4];
            #pragma unroll
            for (int mt = 0; mt < 2; mt++)
                ldsm4(ah[mt], smb + (aRow + mt * 16) * 128 + ((uint32_t)(ck ^ aSel) << 4));
            const int bc = s * 2 + bcLoc;
            uint32_t bh[4][2], bl[4][2], t[4];
            #pragma unroll
            for (int pp = 0; pp < 2; pp++) {
                const int n = wN + 16 * pp + bnLoc;
                const uint32_t ba = wb + n * 128 + ((uint32_t)(bc ^ (n & 7)) << 4);
                ldsm4(t, ba);
                bh[2*pp][0]=t[0]; bh[2*pp][1]=t[1]; bh[2*pp+1][0]=t[2]; bh[2*pp+1][1]=t[3];
                ldsm4(t, ba + 16384);
                bl[2*pp][0]=t[0]; bl[2*pp][1]=t[1]; bl[2*pp+1][0]=t[2]; bl[2*pp+1][1]=t[3];
            }
            #pragma unroll
            for (int mt = 0; mt < 2; mt++) {
                float* am = acc + mt * 16;
                #pragma unroll
                for (int u = 0; u < 4; u++) mma_f16(am + 4*u, ah[mt], bh[u]);
                #pragma unroll
                for (int u = 0; u < 4; u++) mma_f16(am + 4*u, ah[mt], bl[u]);
            }
        }
        #pragma unroll
        for (int mt = 0; mt < 2; mt++) {
            const int r0 = wM + mt * 16 + (l >> 2);
            #pragma unroll
            for (int j = 0; j < 4; j++) {
                const int col = nt * 128 + wN + j * 8 + (l & 3) * 2;
                const float b0 = *(const float*)(sm + 73728 + col * 4);
                const float b1 = *(const float*)(sm + 73728 + col * 4 + 4);
                const int q = mt * 16 + j * 4;
                float v00 = acc[q+0] + b0, v01 = acc[q+1] + b1;
                float v10 = acc[q+2] + b0, v11 = acc[q+3] + b1;
                v00 = v00 > 0.f ? v00 : expm1f(v00);
                v01 = v01 > 0.f ? v01 : expm1f(v01);
                v10 = v10 > 0.f ? v10 : expm1f(v10);
                v11 = v11 > 0.f ? v11 : expm1f(v11);
                *(uint32_t*)(out + (base + r0) * 512 + col)     = packh2(__float2half_rn(v00), __float2half_rn(v01));
                *(uint32_t*)(out + (base + r0 + 8) * 512 + col) = packh2(__float2half_rn(v10), __float2half_rn(v11));
            }
        }
    }
}

// ============================ Layer 2: K=512 -> 512 (ELU), single-fp16 W ============================
__global__ void __launch_bounds__(256, 2)
mid512_kernel(const __half* __restrict__ in, const float* __restrict__ bias,
              __half* __restrict__ out)
{
    extern __shared__ char sm[];
    constexpr int KT = 8, NG = 2, NITER = NG * KT, WOFF = 32768;
    constexpr int BIASOFF = 81920;

    const int tid = threadIdx.x, wid = tid >> 5, l = tid & 31;
    const long base = (long)blockIdx.x * 64;
    const uint32_t smb = smem_u32(sm);

    // per-thread prefetch bases
    const int pr = tid >> 3, pc = tid & 7;
    const uint32_t swz = ((uint32_t)(pc ^ (pr & 7)) << 4);
    const __half* aS = in + (base + pr) * 512 + pc * 8;          // + kt*64 + i*16384
    const uint32_t aD = smb + pr * 128 + swz;                    // + buf*8192 + i*4096
    const __half* wS = g_Whi + WOFF + (long)pr * 512 + pc * 8;   // + ng*131072 + kt*64 + j*16384
    const uint32_t wD = smb + 16384 + pr * 128 + swz;            // + buf*32768 + j*4096

    auto prefetch = [&](int it, int buf) {
        const int ng = it >> 3, kt = it & 7;
        const __half* as = aS + kt * 64;
        const uint32_t ad = aD + buf * 8192;
        CP16(ad,        as);
        CP16(ad + 4096, as + 16384);
        const __half* ws = wS + ng * 131072 + kt * 64;
        const uint32_t wd = wD + buf * 32768;
        #pragma unroll
        for (int j = 0; j < 8; j++) CP16(wd + j * 4096, ws + j * 16384);
    };

    prefetch(0, 0); CP_COMMIT();
    for (int i = tid; i < 512; i += 256) *(float*)(sm + BIASOFF + i * 4) = bias[i];

    const int wM = (wid & 1) * 32, wN = (wid >> 1) * 32;
    const int aRow = wM + (l & 15), aCk = l >> 4;
    const uint32_t aSel = (uint32_t)(aRow & 7);
    const int bnLoc = (l & 7) | ((l & 16) >> 1), bcLoc = (l >> 3) & 1;

    float acc[64];

    #pragma unroll 1
    for (int ng = 0; ng < NG; ++ng) {
        #pragma unroll
        for (int q = 0; q < 64; q++) acc[q] = 0.0f;

        #pragma unroll 2
        for (int kt = 0; kt < KT; ++kt) {
            const int it = ng * KT + kt;
            CP_WAIT0();
            __syncthreads();
            if (it + 1 < NITER) { prefetch(it + 1, (kt + 1) & 1); CP_COMMIT(); }
            const uint32_t ab = smb + (kt & 1) * 8192;
            const uint32_t wb = smb + 16384 + (kt & 1) * 32768;
            #pragma unroll
            for (int s = 0; s < 4; s++) {
                const int ck = s * 2 + aCk;
                uint32_t ah[2][4];
                #pragma unroll
                for (int mt = 0; mt < 2; mt++)
                    ldsm4(ah[mt], ab + (aRow + mt * 16) * 128 + ((uint32_t)(ck ^ aSel) << 4));
                const int bc = s * 2 + bcLoc;
                uint32_t bh[8][2], t[4];
                #pragma unroll
                for (int tl = 0; tl < 2; tl++) {
                    #pragma unroll
                    for (int pp = 0; pp < 2; pp++) {
                        const int n = tl * 128 + wN + 16 * pp + bnLoc;
                        const uint32_t ba = wb + n * 128 + ((uint32_t)(bc ^ (n & 7)) << 4);
                        ldsm4(t, ba);
                        bh[tl*4 + 2*pp][0]=t[0]; bh[tl*4 + 2*pp][1]=t[1];
                        bh[tl*4 + 2*pp+1][0]=t[2]; bh[tl*4 + 2*pp+1][1]=t[3];
                    }
                }
                #pragma unroll
                for (int mt = 0; mt < 2; mt++) {
                    float* am = acc + mt * 32;
                    #pragma unroll
                    for (int u = 0; u < 8; u++) mma_f16(am + 4*u, ah[mt], bh[u]);
                }
            }
        }
        #pragma unroll
        for (int mt = 0; mt < 2; mt++) {
            const int r0 = wM + mt * 16 + (l >> 2);
            #pragma unroll
            for (int tl = 0; tl < 2; tl++) {
                #pragma unroll
                for (int j = 0; j < 4; j++) {
                    const int col = ng * 256 + tl * 128 + wN + j * 8 + (l & 3) * 2;
                    const float b0 = *(const float*)(sm + BIASOFF + col * 4);
                    const float b1 = *(const float*)(sm + BIASOFF + col * 4 + 4);
                    const int q = mt * 32 + tl * 16 + j * 4;
                    float v00 = acc[q+0] + b0, v01 = acc[q+1] + b1;
                    float v10 = acc[q+2] + b0, v11 = acc[q+3] + b1;
                    v00 = v00 > 0.f ? v00 : expm1f(v00);
                    v01 = v01 > 0.f ? v01 : expm1f(v01);
                    v10 = v10 > 0.f ? v10 : expm1f(v10);
                    v11 = v11 > 0.f ? v11 : expm1f(v11);
                    *(uint32_t*)(out + (base + r0) * 512 + col)     = packh2(__float2half_rn(v00), __float2half_rn(v01));
                    *(uint32_t*)(out + (base + r0 + 8) * 512 + col) = packh2(__float2half_rn(v10), __float2half_rn(v11));
                }
            }
        }
    }
}

// ============================ Fused L3+L4: K=512 -> 256 (ELU) -> 64 -> -(x.z)^2 ============================
__global__ void __launch_bounds__(256, 2)
l34_kernel(const __half* __restrict__ in, const float* __restrict__ bias3,
           const float* __restrict__ bias4, const float* __restrict__ x,
           float* __restrict__ outv)
{
    extern __shared__ char sm[];
    constexpr int KT = 8, WOFF3 = 294912, WOFF4 = 425984;
    constexpr int ACT3 = 16384, BIAS3 = 81920, BIAS4 = 82944, ZSUM = 83200;

    const int tid = threadIdx.x, wid = tid >> 5, l = tid & 31;
    const long base = (long)blockIdx.x * 64;
    const uint32_t smb = smem_u32(sm);

    // per-thread prefetch bases
    const int pr = tid >> 3, pc = tid & 7;
    const uint32_t swz = ((uint32_t)(pc ^ (pr & 7)) << 4);
    const __half* aS = in + (base + pr) * 512 + pc * 8;            // + kt*64 + i*16384
    const uint32_t aD = smb + pr * 128 + swz;                      // + buf*8192 + i*4096
    const __half* w3S = g_Whi + WOFF3 + (long)pr * 512 + pc * 8;   // + kt*64 + j*16384
    const uint32_t w3D = smb + 16384 + pr * 128 + swz;             // + buf*32768 + j*4096
    const __half* w4Sh = g_Whi + WOFF4 + pr * 256 + pc * 8;        // + kc*64 + m*8192
    const __half* w4Sl = g_Wlo + WOFF4 + pr * 256 + pc * 8;
    const uint32_t w4D = smb + pr * 128 + swz;                     // + plane*8192 + m*4096

    auto prefetch = [&](int kt, int buf) {
        const __half* as = aS + kt * 64;
        const uint32_t ad = aD + buf * 8192;
        CP16(ad,        as);
        CP16(ad + 4096, as + 16384);
        const __half* ws = w3S + kt * 64;
        const uint32_t wd = w3D + buf * 32768;
        #pragma unroll
        for (int j = 0; j < 8; j++) CP16(wd + j * 4096, ws + j * 16384);
    };

    prefetch(0, 0); CP_COMMIT();
    for (int i = tid; i < 256; i += 256) *(float*)(sm + BIAS3 + i * 4) = bias3[i];
    if (tid < 64) *(float*)(sm + BIAS4 + tid * 4) = bias4[tid];

    const int wM = (wid & 1) * 32, wN = (wid >> 1) * 32;
    const int aRow = wM + (l & 15), aCk = l >> 4;
    const uint32_t aSel = (uint32_t)(aRow & 7);
    const int bnLoc = (l & 7) | ((l & 16) >> 1), bcLoc = (l >> 3) & 1;

    // ---- L3 GEMM ----
    float acc[64];
    #pragma unroll
    for (int q = 0; q < 64; q++) acc[q] = 0.0f;

    #pragma unroll 2
    for (int kt = 0; kt < KT; ++kt) {
        CP_WAIT0();
        __syncthreads();
        if (kt + 1 < KT) { prefetch(kt + 1, (kt + 1) & 1); CP_COMMIT(); }
        const uint32_t ab = smb + (kt & 1) * 8192;
        const uint32_t wb = smb + 16384 + (kt & 1) * 32768;
        #pragma unroll
        for (int s = 0; s < 4; s++) {
            const int ck = s * 2 + aCk;
            uint32_t ah[2][4];
            #pragma unroll
            for (int mt = 0; mt < 2; mt++)
                ldsm4(ah[mt], ab + (aRow + mt * 16) * 128 + ((uint32_t)(ck ^ aSel) << 4));
            const int bc = s * 2 + bcLoc;
            uint32_t bh[8][2], t[4];
            #pragma unroll
            for (int tl = 0; tl < 2; tl++) {
                #pragma unroll
                for (int pp = 0; pp < 2; pp++) {
                    const int n = tl * 128 + wN + 16 * pp + bnLoc;
                    const uint32_t ba = wb + n * 128 + ((uint32_t)(bc ^ (n & 7)) << 4);
                    ldsm4(t, ba);
                    bh[tl*4 + 2*pp][0]=t[0]; bh[tl*4 + 2*pp][1]=t[1];
                    bh[tl*4 + 2*pp+1][0]=t[2]; bh[tl*4 + 2*pp+1][1]=t[3];
                }
            }
            #pragma unroll
            for (int mt = 0; mt < 2; mt++) {
                float* am = acc + mt * 32;
                #pragma unroll
                for (int u = 0; u < 8; u++) mma_f16(am + 4*u, ah[mt], bh[u]);
            }
        }
    }

    // ---- act3 (bias+ELU) -> smem (row stride 512B, 16B-chunk swizzle) ----
    #pragma unroll
    for (int mt = 0; mt < 2; mt++) {
        const int r0 = wM + mt * 16 + (l >> 2);
        #pragma unroll
        for (int tl = 0; tl < 2; tl++) {
            #pragma unroll
            for (int j = 0; j < 4; j++) {
                const int col = tl * 128 + wN + j * 8 + (l & 3) * 2;
                const float b0 = *(const float*)(sm + BIAS3 + col * 4);
                const float b1 = *(const float*)(sm + BIAS3 + col * 4 + 4);
                const int q = mt * 32 + tl * 16 + j * 4;
                float v00 = acc[q+0] + b0, v01 = acc[q+1] + b1;
                float v10 = acc[q+2] + b0, v11 = acc[q+3] + b1;
                v00 = v00 > 0.f ? v00 : expm1f(v00);
                v01 = v01 > 0.f ? v01 : expm1f(v01);
                v10 = v10 > 0.f ? v10 : expm1f(v10);
                v11 = v11 > 0.f ? v11 : expm1f(v11);
                const int c16 = col >> 3;
                const int wi = (col & 7) * 2;
                const uint32_t a0 = ACT3 + r0 * 512 + ((uint32_t)(c16 ^ (r0 & 7)) << 4) + wi;
                const uint32_t a1 = ACT3 + (r0 + 8) * 512 + ((uint32_t)(c16 ^ ((r0 + 8) & 7)) << 4) + wi;
                *(uint32_t*)(sm + a0) = packh2(__float2half_rn(v00), __float2half_rn(v01));
                *(uint32_t*)(sm + a1) = packh2(__float2half_rn(v10), __float2half_rn(v11));
            }
        }
    }
    __syncthreads();

    // ---- L4 GEMM: z = act3 . W4^T (W4 hi/lo exact), streamed in 4 chunks ----
    const int wN4 = (wid >> 1) * 16;
    float acc4[16];
    #pragma unroll
    for (int q = 0; q < 16; q++) acc4[q] = 0.0f;

    #pragma unroll 1
    for (int kc = 0; kc < 4; ++kc) {
        {
            const __half* sh = w4Sh + kc * 64;
            const __half* sl = w4Sl + kc * 64;
            CP16(w4D,                 sh);
            CP16(w4D + 4096,          sh + 8192);
            CP16(w4D + 8192,          sl);
            CP16(w4D + 8192 + 4096,   sl + 8192);
        }
        CP_COMMIT(); CP_WAIT0();
        __syncthreads();
        #pragma unroll
        for (int s = 0; s < 4; s++) {
            const int ckk = kc * 8 + s * 2 + aCk;
            uint32_t ah[2][4];
            #pragma unroll
            for (int mt = 0; mt < 2; mt++)
                ldsm4(ah[mt], smb + ACT3 + (aRow + mt * 16) * 512 + ((uint32_t)(ckk ^ aSel) << 4));
            const int bc = s * 2 + bcLoc;
            uint32_t bh[2][2], bl[2][2], t[4];
            {
                const int n = wN4 + bnLoc;
                const uint32_t ba = smb + n * 128 + ((uint32_t)(bc ^ (n & 7)) << 4);
                ldsm4(t, ba);
                bh[0][0]=t[0]; bh[0][1]=t[1]; bh[1][0]=t[2]; bh[1][1]=t[3];
                ldsm4(t, ba + 8192);
                bl[0][0]=t[0]; bl[0][1]=t[1]; bl[1][0]=t[2]; bl[1][1]=t[3];
            }
            #pragma unroll
            for (int mt = 0; mt < 2; mt++) {
                float* am = acc4 + mt * 8;
                mma_f16(am + 0, ah[mt], bh[0]);
                mma_f16(am + 4, ah[mt], bh[1]);
                mma_f16(am + 0, ah[mt], bl[0]);
                mma_f16(am + 4, ah[mt], bl[1]);
            }
        }
        __syncthreads();
    }

    // ---- fused dot: out = -(x . z)^2 ----
    float* zsum = (float*)(sm + ZSUM);
    #pragma unroll
    for (int mt = 0; mt < 2; mt++) {
        const int r0 = wM + mt * 16 + (l >> 2);
        float p0 = 0.0f, p1 = 0.0f;
        #pragma unroll
        for (int u = 0; u < 2; u++) {
            const int col = wN4 + u * 8 + (l & 3) * 2;
            const float b0 = *(const float*)(sm + BIAS4 + col * 4);
            const float b1 = *(const float*)(sm + BIAS4 + col * 4 + 4);
            const int q = mt * 8 + u * 4;
            const float2 x0 = *(const float2*)(x + (base + r0) * 64 + col);
            const float2 x1 = *(const float2*)(x + (base + r0 + 8) * 64 + col);
            p0 += (acc4[q+0] + b0) * x0.x + (acc4[q+1] + b1) * x0.y;
            p1 += (acc4[q+2] + b0) * x1.x + (acc4[q+3] + b1) * x1.y;
        }
        p0 += __shfl_xor_sync(0xFFFFFFFF, p0, 1);
        p0 += __shfl_xor_sync(0xFFFFFFFF, p0, 2);
        p1 += __shfl_xor_sync(0xFFFFFFFF, p1, 1);
        p1 += __shfl_xor_sync(0xFFFFFFFF, p1, 2);
        if ((l & 3) == 0) {
            zsum[r0 * 4 + (wid >> 1)]       = p0;
            zsum[(r0 + 8) * 4 + (wid >> 1)] = p1;
        }
    }
    __syncthreads();
    if (tid < 64) {
        const float s = zsum[tid * 4] + zsum[tid * 4 + 1] + zsum[tid * 4 + 2] + zsum[tid * 4 + 3];
        outv[base + tid] = -s * s;
    }
}

extern "C" void kernel_launch(void* const* d_in, const int* in_sizes, int n_in,
                              void* d_out, int out_size)
{
    const float* x  = (const float*)d_in[0];
    const float* W1 = (const float*)d_in[1];
    const float* b1 = (const float*)d_in[2];
    const float* W2 = (const float*)d_in[3];
    const float* b2 = (const float*)d_in[4];
    const float* W3 = (const float*)d_in[5];
    const float* b3 = (const float*)d_in[6];
    const float* W4 = (const float*)d_in[7];
    const float* b4 = (const float*)d_in[8];
    float* out = (float*)d_out;

    __half *actA, *actB;
    cudaGetSymbolAddress((void**)&actA, g_actA);
    cudaGetSymbolAddress((void**)&actB, g_actB);

    split_all<<<(442368 + 511) / 512, 512>>>(W1, W2, W3, W4);

    constexpr int SZ1 = 75776;
    constexpr int SZM5 = 83968;
    constexpr int SZ34 = 84224;
    cudaFuncSetAttribute(l1_kernel,     cudaFuncAttributeMaxDynamicSharedMemorySize, SZ1);
    cudaFuncSetAttribute(mid512_kernel, cudaFuncAttributeMaxDynamicSharedMemorySize, SZM5);
    cudaFuncSetAttribute(l34_kernel,    cudaFuncAttributeMaxDynamicSharedMemorySize, SZ34);

    const int grid = 65536 / 64;  // 1024
    l1_kernel<<<grid, 256, SZ1>>>(x, b1, actA);
    mid512_kernel<<<grid, 256, SZM5>>>(actA, b2, actB);
    l34_kernel<<<grid, 256, SZ34>>>(actB, b3, b4, x, out);
}

// round 15
// speedup vs baseline: 1.5757x; 1.0539x over previous
#include <cuda_runtime.h>
#include <cuda_fp16.h>
#include <cstdint>

// value[b] = -( x[b] . MLP(x[b]) )^2 — fp16 HMMA GEMM chain.
// R15: ALL weights single fp16 (error budget: ~7.0e-4 < 1e-3).
//      W4 resident in smem (loaded once, overlapped) -> barrier-free L4.

__device__ __half g_Whi[442368];
__device__ __half g_Wlo[442368];      // kept for layout compat; only split kernel writes
__device__ __half g_actA[65536UL * 512];
__device__ __half g_actB[65536UL * 512];

__device__ __forceinline__ uint32_t smem_u32(const void* p) {
    uint32_t a;
    asm("{ .reg .u64 t; cvta.to.shared.u64 t, %1; cvt.u32.u64 %0, t; }" : "=r"(a) : "l"(p));
    return a;
}
__device__ __forceinline__ void ldsm4(uint32_t* r, uint32_t addr) {
    asm volatile("ldmatrix.sync.aligned.m8n8.x4.shared.b16 {%0,%1,%2,%3}, [%4];"
        : "=r"(r[0]), "=r"(r[1]), "=r"(r[2]), "=r"(r[3]) : "r"(addr));
}
__device__ __forceinline__ void mma_f16(float* c, const uint32_t* a, const uint32_t* b) {
    asm volatile("mma.sync.aligned.m16n8k16.row.col.f32.f16.f16.f32 "
        "{%0,%1,%2,%3}, {%4,%5,%6,%7}, {%8,%9}, {%0,%1,%2,%3};"
        : "+f"(c[0]), "+f"(c[1]), "+f"(c[2]), "+f"(c[3])
        : "r"(a[0]), "r"(a[1]), "r"(a[2]), "r"(a[3]), "r"(b[0]), "r"(b[1]));
}
#define CP16(dst, src)  asm volatile("cp.async.cg.shared.global [%0], [%1], 16;" :: "r"(dst), "l"(src))
#define CP_COMMIT()     asm volatile("cp.async.commit_group;" ::: "memory")
#define CP_WAIT0()      asm volatile("cp.async.wait_group 0;" ::: "memory")

__device__ __forceinline__ uint32_t packh2(__half a, __half b) {
    return (uint32_t)__half_as_ushort(a) | ((uint32_t)__half_as_ushort(b) << 16);
}
__device__ __forceinline__ void split1h(float v, __half& h, __half& l) {
    h = __float2half_rn(v);
    l = __float2half_rn(v - __half2float(h));
}

__global__ void split_all(const float* __restrict__ W1, const float* __restrict__ W2,
                          const float* __restrict__ W3, const float* __restrict__ W4) {
    int i = blockIdx.x * blockDim.x + threadIdx.x;
    if (i >= 442368) return;
    float w;
    if (i < 32768)       w = W1[i];
    else if (i < 294912) w = W2[i - 32768];
    else if (i < 425984) w = W3[i - 294912];
    else                 w = W4[i - 425984];
    __half h, l; split1h(w, h, l);
    g_Whi[i] = h; g_Wlo[i] = l;
}

// ============================ Layer 1: x(f32,K=64) -> 512, ELU (W1 single) ============================
__global__ void __launch_bounds__(256, 2)
l1_kernel(const float* __restrict__ x, const float* __restrict__ bias,
          __half* __restrict__ out)
{
    extern __shared__ char sm[];
    // [0,8192) A | [8192,40960) W bufs 2x16K | [40960,43008) bias
    const int tid = threadIdx.x, wid = tid >> 5, l = tid & 31;
    const long base = (long)blockIdx.x * 64;
    const uint32_t smb = smem_u32(sm);

    const int pr = tid >> 3, pc = tid & 7;
    const uint32_t swz = ((uint32_t)(pc ^ (pr & 7)) << 4);
    const __half* wS = g_Whi + pr * 64 + pc * 8;       // + nt*8192 + jj*2048
    const uint32_t wD = smb + 8192 + pr * 128 + swz;   // + buf*16384 + jj*4096

    auto prefW = [&](int nt, int buf) {
        const int so = nt * 8192;
        const uint32_t wd = wD + buf * 16384;
        #pragma unroll
        for (int jj = 0; jj < 4; jj++) CP16(wd + jj * 4096, wS + so + jj * 2048);
    };

    prefW(0, 0); CP_COMMIT();

    #pragma unroll
    for (int i = tid; i < 1024; i += 256) {
        const int r = i >> 4, k4 = (i & 15) * 4;
        const int c = k4 >> 3, wi = (k4 & 4) << 1;
        const float4 v = *(const float4*)(x + (base + r) * 64 + k4);
        const uint32_t off = r * 128 + ((uint32_t)(c ^ (r & 7)) << 4) + wi;
        *(uint32_t*)(sm + off)     = packh2(__float2half_rn(v.x), __float2half_rn(v.y));
        *(uint32_t*)(sm + off + 4) = packh2(__float2half_rn(v.z), __float2half_rn(v.w));
    }
    for (int i = tid; i < 512; i += 256) *(float*)(sm + 40960 + i * 4) = bias[i];

    const int wM = (wid & 1) * 32, wN = (wid >> 1) * 32;
    const int aRow = wM + (l & 15), aCk = l >> 4;
    const uint32_t aSel = (uint32_t)(aRow & 7);
    const int bnLoc = (l & 7) | ((l & 16) >> 1), bcLoc = (l >> 3) & 1;

    #pragma unroll 2
    for (int nt = 0; nt < 4; nt++) {
        CP_WAIT0();
        __syncthreads();
        if (nt + 1 < 4) { prefW(nt + 1, (nt + 1) & 1); CP_COMMIT(); }
        const uint32_t wb = smb + 8192 + (nt & 1) * 16384;

        float acc[32];
        #pragma unroll
        for (int q = 0; q < 32; q++) acc[q] = 0.0f;

        #pragma unroll
        for (int s = 0; s < 4; s++) {
            const int ck = s * 2 + aCk;
            uint32_t ah[2][4];
            #pragma unroll
            for (int mt = 0; mt < 2; mt++)
                ldsm4(ah[mt], smb + (aRow + mt * 16) * 128 + ((uint32_t)(ck ^ aSel) << 4));
            const int bc = s * 2 + bcLoc;
            uint32_t bh[4][2], t[4];
            #pragma unroll
            for (int pp = 0; pp < 2; pp++) {
                const int n = wN + 16 * pp + bnLoc;
                const uint32_t ba = wb + n * 128 + ((uint32_t)(bc ^ (n & 7)) << 4);
                ldsm4(t, ba);
                bh[2*pp][0]=t[0]; bh[2*pp][1]=t[1]; bh[2*pp+1][0]=t[2]; bh[2*pp+1][1]=t[3];
            }
            #pragma unroll
            for (int mt = 0; mt < 2; mt++) {
                float* am = acc + mt * 16;
                #pragma unroll
                for (int u = 0; u < 4; u++) mma_f16(am + 4*u, ah[mt], bh[u]);
            }
        }
        #pragma unroll
        for (int mt = 0; mt < 2; mt++) {
            const int r0 = wM + mt * 16 + (l >> 2);
            #pragma unroll
            for (int j = 0; j < 4; j++) {
                const int col = nt * 128 + wN + j * 8 + (l & 3) * 2;
                const float b0 = *(const float*)(sm + 40960 + col * 4);
                const float b1 = *(const float*)(sm + 40960 + col * 4 + 4);
                const int q = mt * 16 + j * 4;
                float v00 = acc[q+0] + b0, v01 = acc[q+1] + b1;
                float v10 = acc[q+2] + b0, v11 = acc[q+3] + b1;
                v00 = v00 > 0.f ? v00 : expm1f(v00);
                v01 = v01 > 0.f ? v01 : expm1f(v01);
                v10 = v10 > 0.f ? v10 : expm1f(v10);
                v11 = v11 > 0.f ? v11 : expm1f(v11);
                *(uint32_t*)(out + (base + r0) * 512 + col)     = packh2(__float2half_rn(v00), __float2half_rn(v01));
                *(uint32_t*)(out + (base + r0 + 8) * 512 + col) = packh2(__float2half_rn(v10), __float2half_rn(v11));
            }
        }
    }
}

// ============================ Layer 2: K=512 -> 512 (ELU), single-fp16 W ============================
__global__ void __launch_bounds__(256, 2)
mid512_kernel(const __half* __restrict__ in, const float* __restrict__ bias,
              __half* __restrict__ out)
{
    extern __shared__ char sm[];
    constexpr int KT = 8, NG = 2, NITER = NG * KT, WOFF = 32768;
    constexpr int BIASOFF = 81920;

    const int tid = threadIdx.x, wid = tid >> 5, l = tid & 31;
    const long base = (long)blockIdx.x * 64;
    const uint32_t smb = smem_u32(sm);

    const int pr = tid >> 3, pc = tid & 7;
    const uint32_t swz = ((uint32_t)(pc ^ (pr & 7)) << 4);
    const __half* aS = in + (base + pr) * 512 + pc * 8;
    const uint32_t aD = smb + pr * 128 + swz;
    const __half* wS = g_Whi + WOFF + (long)pr * 512 + pc * 8;
    const uint32_t wD = smb + 16384 + pr * 128 + swz;

    auto prefetch = [&](int it, int buf) {
        const int ng = it >> 3, kt = it & 7;
        const __half* as = aS + kt * 64;
        const uint32_t ad = aD + buf * 8192;
        CP16(ad,        as);
        CP16(ad + 4096, as + 16384);
        const __half* ws = wS + ng * 131072 + kt * 64;
        const uint32_t wd = wD + buf * 32768;
        #pragma unroll
        for (int j = 0; j < 8; j++) CP16(wd + j * 4096, ws + j * 16384);
    };

    prefetch(0, 0); CP_COMMIT();
    for (int i = tid; i < 512; i += 256) *(float*)(sm + BIASOFF + i * 4) = bias[i];

    const int wM = (wid & 1) * 32, wN = (wid >> 1) * 32;
    const int aRow = wM + (l & 15), aCk = l >> 4;
    const uint32_t aSel = (uint32_t)(aRow & 7);
    const int bnLoc = (l & 7) | ((l & 16) >> 1), bcLoc = (l >> 3) & 1;

    float acc[64];

    #pragma unroll 1
    for (int ng = 0; ng < NG; ++ng) {
        #pragma unroll
        for (int q = 0; q < 64; q++) acc[q] = 0.0f;

        #pragma unroll 2
        for (int kt = 0; kt < KT; ++kt) {
            const int it = ng * KT + kt;
            CP_WAIT0();
            __syncthreads();
            if (it + 1 < NITER) { prefetch(it + 1, (kt + 1) & 1); CP_COMMIT(); }
            const uint32_t ab = smb + (kt & 1) * 8192;
            const uint32_t wb = smb + 16384 + (kt & 1) * 32768;
            #pragma unroll
            for (int s = 0; s < 4; s++) {
                const int ck = s * 2 + aCk;
                uint32_t ah[2][4];
                #pragma unroll
                for (int mt = 0; mt < 2; mt++)
                    ldsm4(ah[mt], ab + (aRow + mt * 16) * 128 + ((uint32_t)(ck ^ aSel) << 4));
                const int bc = s * 2 + bcLoc;
                uint32_t bh[8][2], t[4];
                #pragma unroll
                for (int tl = 0; tl < 2; tl++) {
                    #pragma unroll
                    for (int pp = 0; pp < 2; pp++) {
                        const int n = tl * 128 + wN + 16 * pp + bnLoc;
                        const uint32_t ba = wb + n * 128 + ((uint32_t)(bc ^ (n & 7)) << 4);
                        ldsm4(t, ba);
                        bh[tl*4 + 2*pp][0]=t[0]; bh[tl*4 + 2*pp][1]=t[1];
                        bh[tl*4 + 2*pp+1][0]=t[2]; bh[tl*4 + 2*pp+1][1]=t[3];
                    }
                }
                #pragma unroll
                for (int mt = 0; mt < 2; mt++) {
                    float* am = acc + mt * 32;
                    #pragma unroll
                    for (int u = 0; u < 8; u++) mma_f16(am + 4*u, ah[mt], bh[u]);
                }
            }
        }
        #pragma unroll
        for (int mt = 0; mt < 2; mt++) {
            const int r0 = wM + mt * 16 + (l >> 2);
            #pragma unroll
            for (int tl = 0; tl < 2; tl++) {
                #pragma unroll
                for (int j = 0; j < 4; j++) {
                    const int col = ng * 256 + tl * 128 + wN + j * 8 + (l & 3) * 2;
                    const float b0 = *(const float*)(sm + BIASOFF + col * 4);
                    const float b1 = *(const float*)(sm + BIASOFF + col * 4 + 4);
                    const int q = mt * 32 + tl * 16 + j * 4;
                    float v00 = acc[q+0] + b0, v01 = acc[q+1] + b1;
                    float v10 = acc[q+2] + b0, v11 = acc[q+3] + b1;
                    v00 = v00 > 0.f ? v00 : expm1f(v00);
                    v01 = v01 > 0.f ? v01 : expm1f(v01);
                    v10 = v10 > 0.f ? v10 : expm1f(v10);
                    v11 = v11 > 0.f ? v11 : expm1f(v11);
                    *(uint32_t*)(out + (base + r0) * 512 + col)     = packh2(__float2half_rn(v00), __float2half_rn(v01));
                    *(uint32_t*)(out + (base + r0 + 8) * 512 + col) = packh2(__float2half_rn(v10), __float2half_rn(v11));
                }
            }
        }
    }
}

// ============================ Fused L3+L4: K=512 -> 256 (ELU) -> 64 -> -(x.z)^2 ============================
// W4 single fp16, resident in dead W3-buf1 region -> barrier-free L4 GEMM.
__global__ void __launch_bounds__(256, 2)
l34_kernel(const __half* __restrict__ in, const float* __restrict__ bias3,
           const float* __restrict__ bias4, const float* __restrict__ x,
           float* __restrict__ outv)
{
    extern __shared__ char sm[];
    constexpr int KT = 8, WOFF3 = 294912, WOFF4 = 425984;
    constexpr int ACT3 = 16384, W4OFF = 49152, BIAS3 = 81920, BIAS4 = 82944, ZSUM = 83200;

    const int tid = threadIdx.x, wid = tid >> 5, l = tid & 31;
    const long base = (long)blockIdx.x * 64;
    const uint32_t smb = smem_u32(sm);

    const int pr = tid >> 3, pc = tid & 7;
    const uint32_t swz = ((uint32_t)(pc ^ (pr & 7)) << 4);
    const __half* aS = in + (base + pr) * 512 + pc * 8;
    const uint32_t aD = smb + pr * 128 + swz;
    const __half* w3S = g_Whi + WOFF3 + (long)pr * 512 + pc * 8;
    const uint32_t w3D = smb + 16384 + pr * 128 + swz;
    // W4 single plane: 64 rows x 32 chunks, row stride 512B
    const __half* w4S = g_Whi + WOFF4 + pr * 256 + pc * 8;        // rows pr, pr+32; chunks pc+8k
    const uint32_t w4D = smb + W4OFF + pr * 512 + ((uint32_t)(pc ^ (pr & 7)) << 4);

    auto prefetch = [&](int kt, int buf) {
        const __half* as = aS + kt * 64;
        const uint32_t ad = aD + buf * 8192;
        CP16(ad,        as);
        CP16(ad + 4096, as + 16384);
        const __half* ws = w3S + kt * 64;
        const uint32_t wd = w3D + buf * 32768;
        #pragma unroll
        for (int j = 0; j < 8; j++) CP16(wd + j * 4096, ws + j * 16384);
    };

    prefetch(0, 0); CP_COMMIT();
    for (int i = tid; i < 256; i += 256) *(float*)(sm + BIAS3 + i * 4) = bias3[i];
    if (tid < 64) *(float*)(sm + BIAS4 + tid * 4) = bias4[tid];

    const int wM = (wid & 1) * 32, wN = (wid >> 1) * 32;
    const int aRow = wM + (l & 15), aCk = l >> 4;
    const uint32_t aSel = (uint32_t)(aRow & 7);
    const int bnLoc = (l & 7) | ((l & 16) >> 1), bcLoc = (l >> 3) & 1;

    // ---- L3 GEMM ----
    float acc[64];
    #pragma unroll
    for (int q = 0; q < 64; q++) acc[q] = 0.0f;

    #pragma unroll 2
    for (int kt = 0; kt < KT; ++kt) {
        CP_WAIT0();
        __syncthreads();
        if (kt + 1 < KT) { prefetch(kt + 1, (kt + 1) & 1); CP_COMMIT(); }
        const uint32_t ab = smb + (kt & 1) * 8192;
        const uint32_t wb = smb + 16384 + (kt & 1) * 32768;
        #pragma unroll
        for (int s = 0; s < 4; s++) {
            const int ck = s * 2 + aCk;
            uint32_t ah[2][4];
            #pragma unroll
            for (int mt = 0; mt < 2; mt++)
                ldsm4(ah[mt], ab + (aRow + mt * 16) * 128 + ((uint32_t)(ck ^ aSel) << 4));
            const int bc = s * 2 + bcLoc;
            uint32_t bh[8][2], t[4];
            #pragma unroll
            for (int tl = 0; tl < 2; tl++) {
                #pragma unroll
                for (int pp = 0; pp < 2; pp++) {
                    const int n = tl * 128 + wN + 16 * pp + bnLoc;
                    const uint32_t ba = wb + n * 128 + ((uint32_t)(bc ^ (n & 7)) << 4);
                    ldsm4(t, ba);
                    bh[tl*4 + 2*pp][0]=t[0]; bh[tl*4 + 2*pp][1]=t[1];
                    bh[tl*4 + 2*pp+1][0]=t[2]; bh[tl*4 + 2*pp+1][1]=t[3];
                }
            }
            #pragma unroll
            for (int mt = 0; mt < 2; mt++) {
                float* am = acc + mt * 32;
                #pragma unroll
                for (int u = 0; u < 8; u++) mma_f16(am + 4*u, ah[mt], bh[u]);
            }
        }
    }

    // ---- all kt=7 reads done before W4 overwrite of buf1 / act3 stores to buf0 ----
    __syncthreads();

    // W4 load (once, 32KB), overlapped with act3 epilogue below.
    #pragma unroll
    for (int r2 = 0; r2 < 2; r2++) {
        #pragma unroll
        for (int k = 0; k < 4; k++)
            CP16(w4D + r2 * 16384 + k * 128, w4S + r2 * 8192 + k * 64);
    }
    CP_COMMIT();

    // ---- act3 (bias+ELU) -> smem (row stride 512B, 16B-chunk swizzle) ----
    #pragma unroll
    for (int mt = 0; mt < 2; mt++) {
        const int r0 = wM + mt * 16 + (l >> 2);
        #pragma unroll
        for (int tl = 0; tl < 2; tl++) {
            #pragma unroll
            for (int j = 0; j < 4; j++) {
                const int col = tl * 128 + wN + j * 8 + (l & 3) * 2;
                const float b0 = *(const float*)(sm + BIAS3 + col * 4);
                const float b1 = *(const float*)(sm + BIAS3 + col * 4 + 4);
                const int q = mt * 32 + tl * 16 + j * 4;
                float v00 = acc[q+0] + b0, v01 = acc[q+1] + b1;
                float v10 = acc[q+2] + b0, v11 = acc[q+3] + b1;
                v00 = v00 > 0.f ? v00 : expm1f(v00);
                v01 = v01 > 0.f ? v01 : expm1f(v01);
                v10 = v10 > 0.f ? v10 : expm1f(v10);
                v11 = v11 > 0.f ? v11 : expm1f(v11);
                const int c16 = col >> 3;
                const int wi = (col & 7) * 2;
                const uint32_t a0 = ACT3 + r0 * 512 + ((uint32_t)(c16 ^ (r0 & 7)) << 4) + wi;
                const uint32_t a1 = ACT3 + (r0 + 8) * 512 + ((uint32_t)(c16 ^ ((r0 + 8) & 7)) << 4) + wi;
                *(uint32_t*)(sm + a0) = packh2(__float2half_rn(v00), __float2half_rn(v01));
                *(uint32_t*)(sm + a1) = packh2(__float2half_rn(v10), __float2half_rn(v11));
            }
        }
    }
    CP_WAIT0();
    __syncthreads();

    // ---- L4 GEMM: z = act3 . W4^T (+b4), fully resident, no barriers ----
    const int wN4 = (wid >> 1) * 16;
    float acc4[16];
    #pragma unroll
    for (int q = 0; q < 16; q++) acc4[q] = 0.0f;

    #pragma unroll
    for (int s = 0; s < 16; s++) {
        const int ckk = s * 2 + aCk;
        uint32_t ah[2][4];
        #pragma unroll
        for (int mt = 0; mt < 2; mt++)
            ldsm4(ah[mt], smb + ACT3 + (aRow + mt * 16) * 512 + ((uint32_t)(ckk ^ aSel) << 4));
        const int bc = s * 2 + bcLoc;
        uint32_t bh[2][2], t[4];
        {
            const int n = wN4 + bnLoc;
            const uint32_t ba = smb + W4OFF + n * 512 + ((uint32_t)(bc ^ (n & 7)) << 4);
            ldsm4(t, ba);
            bh[0][0]=t[0]; bh[0][1]=t[1]; bh[1][0]=t[2]; bh[1][1]=t[3];
        }
        #pragma unroll
        for (int mt = 0; mt < 2; mt++) {
            float* am = acc4 + mt * 8;
            mma_f16(am + 0, ah[mt], bh[0]);
            mma_f16(am + 4, ah[mt], bh[1]);
        }
    }

    // ---- fused dot: out = -(x . z)^2 ----
    float* zsum = (float*)(sm + ZSUM);
    #pragma unroll
    for (int mt = 0; mt < 2; mt++) {
        const int r0 = wM + mt * 16 + (l >> 2);
        float p0 = 0.0f, p1 = 0.0f;
        #pragma unroll
        for (int u = 0; u < 2; u++) {
            const int col = wN4 + u * 8 + (l & 3) * 2;
            const float b0 = *(const float*)(sm + BIAS4 + col * 4);
            const float b1 = *(const float*)(sm + BIAS4 + col * 4 + 4);
            const int q = mt * 8 + u * 4;
            const float2 x0 = *(const float2*)(x + (base + r0) * 64 + col);
            const float2 x1 = *(const float2*)(x + (base + r0 + 8) * 64 + col);
            p0 += (acc4[q+0] + b0) * x0.x + (acc4[q+1] + b1) * x0.y;
            p1 += (acc4[q+2] + b0) * x1.x + (acc4[q+3] + b1) * x1.y;
        }
        p0 += __shfl_xor_sync(0xFFFFFFFF, p0, 1);
        p0 += __shfl_xor_sync(0xFFFFFFFF, p0, 2);
        p1 += __shfl_xor_sync(0xFFFFFFFF, p1, 1);
        p1 += __shfl_xor_sync(0xFFFFFFFF, p1, 2);
        if ((l & 3) == 0) {
            zsum[r0 * 4 + (wid >> 1)]       = p0;
            zsum[(r0 + 8) * 4 + (wid >> 1)] = p1;
        }
    }
    __syncthreads();
    if (tid < 64) {
        const float s = zsum[tid * 4] + zsum[tid * 4 + 1] + zsum[tid * 4 + 2] + zsum[tid * 4 + 3];
        outv[base + tid] = -s * s;
    }
}

extern "C" void kernel_launch(void* const* d_in, const int* in_sizes, int n_in,
                              void* d_out, int out_size)
{
    const float* x  = (const float*)d_in[0];
    const float* W1 = (const float*)d_in[1];
    const float* b1 = (const float*)d_in[2];
    const float* W2 = (const float*)d_in[3];
    const float* b2 = (const float*)d_in[4];
    const float* W3 = (const float*)d_in[5];
    const float* b3 = (const float*)d_in[6];
    const float* W4 = (const float*)d_in[7];
    const float* b4 = (const float*)d_in[8];
    float* out = (float*)d_out;

    __half *actA, *actB;
    cudaGetSymbolAddress((void**)&actA, g_actA);
    cudaGetSymbolAddress((void**)&actB, g_actB);

    split_all<<<(442368 + 511) / 512, 512>>>(W1, W2, W3, W4);

    constexpr int SZ1 = 43008;   // 8K A + 32K W bufs + 2K bias
    constexpr int SZM5 = 83968;
    constexpr int SZ34 = 84224;
    cudaFuncSetAttribute(l1_kernel,     cudaFuncAttributeMaxDynamicSharedMemorySize, SZ1);
    cudaFuncSetAttribute(mid512_kernel, cudaFuncAttributeMaxDynamicSharedMemorySize, SZM5);
    cudaFuncSetAttribute(l34_kernel,    cudaFuncAttributeMaxDynamicSharedMemorySize, SZ34);

    const int grid = 65536 / 64;  // 1024
    l1_kernel<<<grid, 256, SZ1>>>(x, b1, actA);
    mid512_kernel<<<grid, 256, SZM5>>>(actA, b2, actB);
    l34_kernel<<<grid, 256, SZ34>>>(actB, b3, b4, x, out);
}

// round 16
// speedup vs baseline: 1.5783x; 1.0017x over previous
#include <cuda_runtime.h>
#include <cuda_fp16.h>
#include <cstdint>

// value[b] = -( x[b] . MLP(x[b]) )^2 — fp16 HMMA GEMM chain.
// R16: L1+L2 fused (act1 resident in smem as ldmatrix tiles; phase-2 A-stream
//      and the 128MB act1 gmem round-trip eliminated). All weights single fp16.

__device__ __half g_Whi[442368];
__device__ __half g_act[65536UL * 512];

__device__ __forceinline__ uint32_t smem_u32(const void* p) {
    uint32_t a;
    asm("{ .reg .u64 t; cvta.to.shared.u64 t, %1; cvt.u32.u64 %0, t; }" : "=r"(a) : "l"(p));
    return a;
}
__device__ __forceinline__ void ldsm4(uint32_t* r, uint32_t addr) {
    asm volatile("ldmatrix.sync.aligned.m8n8.x4.shared.b16 {%0,%1,%2,%3}, [%4];"
        : "=r"(r[0]), "=r"(r[1]), "=r"(r[2]), "=r"(r[3]) : "r"(addr));
}
__device__ __forceinline__ void mma_f16(float* c, const uint32_t* a, const uint32_t* b) {
    asm volatile("mma.sync.aligned.m16n8k16.row.col.f32.f16.f16.f32 "
        "{%0,%1,%2,%3}, {%4,%5,%6,%7}, {%8,%9}, {%0,%1,%2,%3};"
        : "+f"(c[0]), "+f"(c[1]), "+f"(c[2]), "+f"(c[3])
        : "r"(a[0]), "r"(a[1]), "r"(a[2]), "r"(a[3]), "r"(b[0]), "r"(b[1]));
}
#define CP16(dst, src)  asm volatile("cp.async.cg.shared.global [%0], [%1], 16;" :: "r"(dst), "l"(src))
#define CP_COMMIT()     asm volatile("cp.async.commit_group;" ::: "memory")
#define CP_WAIT0()      asm volatile("cp.async.wait_group 0;" ::: "memory")

__device__ __forceinline__ uint32_t packh2(__half a, __half b) {
    return (uint32_t)__half_as_ushort(a) | ((uint32_t)__half_as_ushort(b) << 16);
}

__global__ void split_all(const float* __restrict__ W1, const float* __restrict__ W2,
                          const float* __restrict__ W3, const float* __restrict__ W4) {
    int i = blockIdx.x * blockDim.x + threadIdx.x;
    if (i >= 442368) return;
    float w;
    if (i < 32768)       w = W1[i];
    else if (i < 294912) w = W2[i - 32768];
    else if (i < 425984) w = W3[i - 294912];
    else                 w = W4[i - 425984];
    g_Whi[i] = __float2half_rn(w);
}

// ============================ Fused L1+L2: x -> 512 (ELU) -> 512 (ELU) ============================
// smem: [0,64K) act1 (8 tiles x 8KB, 64 cols each) | [64K,72K) x | [72K,104K) W bufs 2x16K
//       [104K,106K) bias1 | [106K,108K) bias2
__global__ void __launch_bounds__(256, 2)
l12_kernel(const float* __restrict__ x, const float* __restrict__ bias1,
           const float* __restrict__ bias2, __half* __restrict__ out)
{
    extern __shared__ char sm[];
    constexpr int ACT1 = 0, XOFF = 65536, WOFF = 73728, BIAS1 = 106496, BIAS2 = 108544;

    const int tid = threadIdx.x, wid = tid >> 5, l = tid & 31;
    const long base = (long)blockIdx.x * 64;
    const uint32_t smb = smem_u32(sm);

    // per-thread prefetch bases
    const int pr = tid >> 3, pc = tid & 7;
    const uint32_t swz = ((uint32_t)(pc ^ (pr & 7)) << 4);
    const __half* w1S = g_Whi + pr * 64 + pc * 8;                 // + nt*8192 + j*2048
    const __half* w2S = g_Whi + 32768 + (long)pr * 512 + pc * 8;  // + ng*65536 + kt*64 + j*16384
    const uint32_t wD = smb + WOFF + pr * 128 + swz;              // + buf*16384 + j*4096

    auto prefW1 = [&](int nt, int buf) {
        const __half* s = w1S + nt * 8192;
        const uint32_t d = wD + buf * 16384;
        #pragma unroll
        for (int j = 0; j < 4; j++) CP16(d + j * 4096, s + j * 2048);
    };
    auto prefW2 = [&](int it, int buf) {
        const int ng = it >> 3, kt = it & 7;
        const __half* s = w2S + ng * 65536 + kt * 64;
        const uint32_t d = wD + buf * 16384;
        #pragma unroll
        for (int j = 0; j < 4; j++) CP16(d + j * 4096, s + j * 16384);
    };

    prefW1(0, 0); CP_COMMIT();

    // x tile -> fp16 smem (swizzled, 128B rows)
    #pragma unroll
    for (int i = tid; i < 1024; i += 256) {
        const int r = i >> 4, k4 = (i & 15) * 4;
        const int c = k4 >> 3, wi = (k4 & 4) << 1;
        const float4 v = *(const float4*)(x + (base + r) * 64 + k4);
        const uint32_t off = XOFF + r * 128 + ((uint32_t)(c ^ (r & 7)) << 4) + wi;
        *(uint32_t*)(sm + off)     = packh2(__float2half_rn(v.x), __float2half_rn(v.y));
        *(uint32_t*)(sm + off + 4) = packh2(__float2half_rn(v.z), __float2half_rn(v.w));
    }
    for (int i = tid; i < 512; i += 256) {
        *(float*)(sm + BIAS1 + i * 4) = bias1[i];
        *(float*)(sm + BIAS2 + i * 4) = bias2[i];
    }

    const int wM = (wid & 1) * 32, wN = (wid >> 1) * 32;
    const int aRow = wM + (l & 15), aCk = l >> 4;
    const uint32_t aSel = (uint32_t)(aRow & 7);
    const int bnLoc = (l & 7) | ((l & 16) >> 1), bcLoc = (l >> 3) & 1;

    // ================= Phase 1: L1 (K=64), epilogue -> act1 smem tiles =================
    #pragma unroll 2
    for (int nt = 0; nt < 4; nt++) {
        CP_WAIT0();
        __syncthreads();
        if (nt < 3) prefW1(nt + 1, (nt + 1) & 1);
        else        prefW2(0, 0);
        CP_COMMIT();
        const uint32_t wb = smb + WOFF + (nt & 1) * 16384;

        float acc[32];
        #pragma unroll
        for (int q = 0; q < 32; q++) acc[q] = 0.0f;

        #pragma unroll
        for (int s = 0; s < 4; s++) {
            const int ck = s * 2 + aCk;
            uint32_t ah[2][4];
            #pragma unroll
            for (int mt = 0; mt < 2; mt++)
                ldsm4(ah[mt], smb + XOFF + (aRow + mt * 16) * 128 + ((uint32_t)(ck ^ aSel) << 4));
            const int bc = s * 2 + bcLoc;
            uint32_t bh[4][2], t[4];
            #pragma unroll
            for (int pp = 0; pp < 2; pp++) {
                const int n = wN + 16 * pp + bnLoc;
                const uint32_t ba = wb + n * 128 + ((uint32_t)(bc ^ (n & 7)) << 4);
                ldsm4(t, ba);
                bh[2*pp][0]=t[0]; bh[2*pp][1]=t[1]; bh[2*pp+1][0]=t[2]; bh[2*pp+1][1]=t[3];
            }
            #pragma unroll
            for (int mt = 0; mt < 2; mt++) {
                float* am = acc + mt * 16;
                #pragma unroll
                for (int u = 0; u < 4; u++) mma_f16(am + 4*u, ah[mt], bh[u]);
            }
        }
        // epilogue: bias+ELU -> act1 tiles (tile t: 64 cols, 128B rows, swizzled)
        #pragma unroll
        for (int mt = 0; mt < 2; mt++) {
            const int r0 = wM + mt * 16 + (l >> 2);
            #pragma unroll
            for (int j = 0; j < 4; j++) {
                const int col = nt * 128 + wN + j * 8 + (l & 3) * 2;
                const float b0 = *(const float*)(sm + BIAS1 + col * 4);
                const float b1 = *(const float*)(sm + BIAS1 + col * 4 + 4);
                const int q = mt * 16 + j * 4;
                float v00 = acc[q+0] + b0, v01 = acc[q+1] + b1;
                float v10 = acc[q+2] + b0, v11 = acc[q+3] + b1;
                v00 = v00 > 0.f ? v00 : expm1f(v00);
                v01 = v01 > 0.f ? v01 : expm1f(v01);
                v10 = v10 > 0.f ? v10 : expm1f(v10);
                v11 = v11 > 0.f ? v11 : expm1f(v11);
                const int tt = col >> 6, lcol = col & 63;
                const int c16 = lcol >> 3, wi = (lcol & 7) * 2;
                const uint32_t a0 = ACT1 + tt * 8192 + r0 * 128 + ((uint32_t)(c16 ^ (r0 & 7)) << 4) + wi;
                const uint32_t a1 = a0 + 1024;   // (r0+8): row +8*128; swizzle sel (r0+8)&7 == r0&7... NO
                // (r0+8)&7 != r0&7 in general -> compute explicitly:
                const uint32_t a1x = ACT1 + tt * 8192 + (r0 + 8) * 128 + ((uint32_t)(c16 ^ ((r0 + 8) & 7)) << 4) + wi;
                (void)a1;
                *(uint32_t*)(sm + a0)  = packh2(__float2half_rn(v00), __float2half_rn(v01));
                *(uint32_t*)(sm + a1x) = packh2(__float2half_rn(v10), __float2half_rn(v11));
            }
        }
    }

    // ================= Phase 2: L2 (K=512, A = act1 resident) =================
    float acc[32];
    #pragma unroll 1
    for (int ng = 0; ng < 4; ++ng) {
        #pragma unroll
        for (int q = 0; q < 32; q++) acc[q] = 0.0f;

        #pragma unroll 2
        for (int kt = 0; kt < 8; ++kt) {
            const int it = ng * 8 + kt;
            CP_WAIT0();
            __syncthreads();
            if (it + 1 < 32) { prefW2(it + 1, (it + 1) & 1); CP_COMMIT(); }
            const uint32_t wb = smb + WOFF + (it & 1) * 16384;
            const uint32_t atile = smb + ACT1 + kt * 8192;
            #pragma unroll
            for (int s = 0; s < 4; s++) {
                const int cc = s * 2 + aCk;
                uint32_t ah[2][4];
                #pragma unroll
                for (int mt = 0; mt < 2; mt++)
                    ldsm4(ah[mt], atile + (aRow + mt * 16) * 128 + ((uint32_t)(cc ^ aSel) << 4));
                const int bc = s * 2 + bcLoc;
                uint32_t bh[4][2], t[4];
                #pragma unroll
                for (int pp = 0; pp < 2; pp++) {
                    const int n = wN + 16 * pp + bnLoc;
                    const uint32_t ba = wb + n * 128 + ((uint32_t)(bc ^ (n & 7)) << 4);
                    ldsm4(t, ba);
                    bh[2*pp][0]=t[0]; bh[2*pp][1]=t[1]; bh[2*pp+1][0]=t[2]; bh[2*pp+1][1]=t[3];
                }
                #pragma unroll
                for (int mt = 0; mt < 2; mt++) {
                    float* am = acc + mt * 16;
                    #pragma unroll
                    for (int u = 0; u < 4; u++) mma_f16(am + 4*u, ah[mt], bh[u]);
                }
            }
            if (kt == 7) {
                #pragma unroll
                for (int mt = 0; mt < 2; mt++) {
                    const int r0 = wM + mt * 16 + (l >> 2);
                    #pragma unroll
                    for (int j = 0; j < 4; j++) {
                        const int col = ng * 128 + wN + j * 8 + (l & 3) * 2;
                        const float b0 = *(const float*)(sm + BIAS2 + col * 4);
                        const float b1 = *(const float*)(sm + BIAS2 + col * 4 + 4);
                        const int q = mt * 16 + j * 4;
                        float v00 = acc[q+0] + b0, v01 = acc[q+1] + b1;
                        float v10 = acc[q+2] + b0, v11 = acc[q+3] + b1;
                        v00 = v00 > 0.f ? v00 : expm1f(v00);
                        v01 = v01 > 0.f ? v01 : expm1f(v01);
                        v10 = v10 > 0.f ? v10 : expm1f(v10);
                        v11 = v11 > 0.f ? v11 : expm1f(v11);
                        *(uint32_t*)(out + (base + r0) * 512 + col)     = packh2(__float2half_rn(v00), __float2half_rn(v01));
                        *(uint32_t*)(out + (base + r0 + 8) * 512 + col) = packh2(__float2half_rn(v10), __float2half_rn(v11));
                    }
                }
            }
        }
    }
}

// ============================ Fused L3+L4 (unchanged from R15) ============================
__global__ void __launch_bounds__(256, 2)
l34_kernel(const __half* __restrict__ in, const float* __restrict__ bias3,
           const float* __restrict__ bias4, const float* __restrict__ x,
           float* __restrict__ outv)
{
    extern __shared__ char sm[];
    constexpr int KT = 8, WOFF3 = 294912, WOFF4 = 425984;
    constexpr int ACT3 = 16384, W4OFF = 49152, BIAS3 = 81920, BIAS4 = 82944, ZSUM = 83200;

    const int tid = threadIdx.x, wid = tid >> 5, l = tid & 31;
    const long base = (long)blockIdx.x * 64;
    const uint32_t smb = smem_u32(sm);

    const int pr = tid >> 3, pc = tid & 7;
    const uint32_t swz = ((uint32_t)(pc ^ (pr & 7)) << 4);
    const __half* aS = in + (base + pr) * 512 + pc * 8;
    const uint32_t aD = smb + pr * 128 + swz;
    const __half* w3S = g_Whi + WOFF3 + (long)pr * 512 + pc * 8;
    const uint32_t w3D = smb + 16384 + pr * 128 + swz;
    const __half* w4S = g_Whi + WOFF4 + pr * 256 + pc * 8;
    const uint32_t w4D = smb + W4OFF + pr * 512 + ((uint32_t)(pc ^ (pr & 7)) << 4);

    auto prefetch = [&](int kt, int buf) {
        const __half* as = aS + kt * 64;
        const uint32_t ad = aD + buf * 8192;
        CP16(ad,        as);
        CP16(ad + 4096, as + 16384);
        const __half* ws = w3S + kt * 64;
        const uint32_t wd = w3D + buf * 32768;
        #pragma unroll
        for (int j = 0; j < 8; j++) CP16(wd + j * 4096, ws + j * 16384);
    };

    prefetch(0, 0); CP_COMMIT();
    for (int i = tid; i < 256; i += 256) *(float*)(sm + BIAS3 + i * 4) = bias3[i];
    if (tid < 64) *(float*)(sm + BIAS4 + tid * 4) = bias4[tid];

    const int wM = (wid & 1) * 32, wN = (wid >> 1) * 32;
    const int aRow = wM + (l & 15), aCk = l >> 4;
    const uint32_t aSel = (uint32_t)(aRow & 7);
    const int bnLoc = (l & 7) | ((l & 16) >> 1), bcLoc = (l >> 3) & 1;

    float acc[64];
    #pragma unroll
    for (int q = 0; q < 64; q++) acc[q] = 0.0f;

    #pragma unroll 2
    for (int kt = 0; kt < KT; ++kt) {
        CP_WAIT0();
        __syncthreads();
        if (kt + 1 < KT) { prefetch(kt + 1, (kt + 1) & 1); CP_COMMIT(); }
        const uint32_t ab = smb + (kt & 1) * 8192;
        const uint32_t wb = smb + 16384 + (kt & 1) * 32768;
        #pragma unroll
        for (int s = 0; s < 4; s++) {
            const int ck = s * 2 + aCk;
            uint32_t ah[2][4];
            #pragma unroll
            for (int mt = 0; mt < 2; mt++)
                ldsm4(ah[mt], ab + (aRow + mt * 16) * 128 + ((uint32_t)(ck ^ aSel) << 4));
            const int bc = s * 2 + bcLoc;
            uint32_t bh[8][2], t[4];
            #pragma unroll
            for (int tl = 0; tl < 2; tl++) {
                #pragma unroll
                for (int pp = 0; pp < 2; pp++) {
                    const int n = tl * 128 + wN + 16 * pp + bnLoc;
                    const uint32_t ba = wb + n * 128 + ((uint32_t)(bc ^ (n & 7)) << 4);
                    ldsm4(t, ba);
                    bh[tl*4 + 2*pp][0]=t[0]; bh[tl*4 + 2*pp][1]=t[1];
                    bh[tl*4 + 2*pp+1][0]=t[2]; bh[tl*4 + 2*pp+1][1]=t[3];
                }
            }
            #pragma unroll
            for (int mt = 0; mt < 2; mt++) {
                float* am = acc + mt * 32;
                #pragma unroll
                for (int u = 0; u < 8; u++) mma_f16(am + 4*u, ah[mt], bh[u]);
            }
        }
    }

    __syncthreads();

    #pragma unroll
    for (int r2 = 0; r2 < 2; r2++) {
        #pragma unroll
        for (int k = 0; k < 4; k++)
            CP16(w4D + r2 * 16384 + k * 128, w4S + r2 * 8192 + k * 64);
    }
    CP_COMMIT();

    #pragma unroll
    for (int mt = 0; mt < 2; mt++) {
        const int r0 = wM + mt * 16 + (l >> 2);
        #pragma unroll
        for (int tl = 0; tl < 2; tl++) {
            #pragma unroll
            for (int j = 0; j < 4; j++) {
                const int col = tl * 128 + wN + j * 8 + (l & 3) * 2;
                const float b0 = *(const float*)(sm + BIAS3 + col * 4);
                const float b1 = *(const float*)(sm + BIAS3 + col * 4 + 4);
                const int q = mt * 32 + tl * 16 + j * 4;
                float v00 = acc[q+0] + b0, v01 = acc[q+1] + b1;
                float v10 = acc[q+2] + b0, v11 = acc[q+3] + b1;
                v00 = v00 > 0.f ? v00 : expm1f(v00);
                v01 = v01 > 0.f ? v01 : expm1f(v01);
                v10 = v10 > 0.f ? v10 : expm1f(v10);
                v11 = v11 > 0.f ? v11 : expm1f(v11);
                const int c16 = col >> 3;
                const int wi = (col & 7) * 2;
                const uint32_t a0 = ACT3 + r0 * 512 + ((uint32_t)(c16 ^ (r0 & 7)) << 4) + wi;
                const uint32_t a1 = ACT3 + (r0 + 8) * 512 + ((uint32_t)(c16 ^ ((r0 + 8) & 7)) << 4) + wi;
                *(uint32_t*)(sm + a0) = packh2(__float2half_rn(v00), __float2half_rn(v01));
                *(uint32_t*)(sm + a1) = packh2(__float2half_rn(v10), __float2half_rn(v11));
            }
        }
    }
    CP_WAIT0();
    __syncthreads();

    const int wN4 = (wid >> 1) * 16;
    float acc4[16];
    #pragma unroll
    for (int q = 0; q < 16; q++) acc4[q] = 0.0f;

    #pragma unroll
    for (int s = 0; s < 16; s++) {
        const int ckk = s * 2 + aCk;
        uint32_t ah[2][4];
        #pragma unroll
        for (int mt = 0; mt < 2; mt++)
            ldsm4(ah[mt], smb + ACT3 + (aRow + mt * 16) * 512 + ((uint32_t)(ckk ^ aSel) << 4));
        const int bc = s * 2 + bcLoc;
        uint32_t bh[2][2], t[4];
        {
            const int n = wN4 + bnLoc;
            const uint32_t ba = smb + W4OFF + n * 512 + ((uint32_t)(bc ^ (n & 7)) << 4);
            ldsm4(t, ba);
            bh[0][0]=t[0]; bh[0][1]=t[1]; bh[1][0]=t[2]; bh[1][1]=t[3];
        }
        #pragma unroll
        for (int mt = 0; mt < 2; mt++) {
            float* am = acc4 + mt * 8;
            mma_f16(am + 0, ah[mt], bh[0]);
            mma_f16(am + 4, ah[mt], bh[1]);
        }
    }

    float* zsum = (float*)(sm + ZSUM);
    #pragma unroll
    for (int mt = 0; mt < 2; mt++) {
        const int r0 = wM + mt * 16 + (l >> 2);
        float p0 = 0.0f, p1 = 0.0f;
        #pragma unroll
        for (int u = 0; u < 2; u++) {
            const int col = wN4 + u * 8 + (l & 3) * 2;
            const float b0 = *(const float*)(sm + BIAS4 + col * 4);
            const float b1 = *(const float*)(sm + BIAS4 + col * 4 + 4);
            const int q = mt * 8 + u * 4;
            const float2 x0 = *(const float2*)(x + (base + r0) * 64 + col);
            const float2 x1 = *(const float2*)(x + (base + r0 + 8) * 64 + col);
            p0 += (acc4[q+0] + b0) * x0.x + (acc4[q+1] + b1) * x0.y;
            p1 += (acc4[q+2] + b0) * x1.x + (acc4[q+3] + b1) * x1.y;
        }
        p0 += __shfl_xor_sync(0xFFFFFFFF, p0, 1);
        p0 += __shfl_xor_sync(0xFFFFFFFF, p0, 2);
        p1 += __shfl_xor_sync(0xFFFFFFFF, p1, 1);
        p1 += __shfl_xor_sync(0xFFFFFFFF, p1, 2);
        if ((l & 3) == 0) {
            zsum[r0 * 4 + (wid >> 1)]       = p0;
            zsum[(r0 + 8) * 4 + (wid >> 1)] = p1;
        }
    }
    __syncthreads();
    if (tid < 64) {
        const float s = zsum[tid * 4] + zsum[tid * 4 + 1] + zsum[tid * 4 + 2] + zsum[tid * 4 + 3];
        outv[base + tid] = -s * s;
    }
}

extern "C" void kernel_launch(void* const* d_in, const int* in_sizes, int n_in,
                              void* d_out, int out_size)
{
    const float* x  = (const float*)d_in[0];
    const float* W1 = (const float*)d_in[1];
    const float* b1 = (const float*)d_in[2];
    const float* W2 = (const float*)d_in[3];
    const float* b2 = (const float*)d_in[4];
    const float* W3 = (const float*)d_in[5];
    const float* b3 = (const float*)d_in[6];
    const float* W4 = (const float*)d_in[7];
    const float* b4 = (const float*)d_in[8];
    float* out = (float*)d_out;

    __half* act;
    cudaGetSymbolAddress((void**)&act, g_act);

    split_all<<<(442368 + 511) / 512, 512>>>(W1, W2, W3, W4);

    constexpr int SZ12 = 110592;  // 64K act1 + 8K x + 32K W bufs + 4K bias
    constexpr int SZ34 = 84224;
    cudaFuncSetAttribute(l12_kernel, cudaFuncAttributeMaxDynamicSharedMemorySize, SZ12);
    cudaFuncSetAttribute(l34_kernel, cudaFuncAttributeMaxDynamicSharedMemorySize, SZ34);

    const int grid = 65536 / 64;  // 1024
    l12_kernel<<<grid, 256, SZ12>>>(x, b1, b2, act);
    l34_kernel<<<grid, 256, SZ34>>>(act, b3, b4, x, out);
}